// round 1
// baseline (speedup 1.0000x reference)
#include <cuda_runtime.h>
#include <cuda_bf16.h>
#include <math.h>

#define BB 2
#define SS 1024
#define HH 768
#define NHD 12
#define HD 64
#define LL 4
#define VV 32000
#define MM (BB*SS)
#define TH (3*HH)

__device__ float g_h[MM * HH];
__device__ float g_qkv[MM * TH];
__device__ float g_a[MM * HH];
__device__ float g_b[MM * 4 * HH];

__global__ void embed_kernel(const int* __restrict__ ids,
                             const float* __restrict__ bpe,
                             const float* __restrict__ pos,
                             float* __restrict__ h)
{
    int row = blockIdx.x;
    int s = row % SS;
    int id = ids[row];
    const float* brow = bpe + (size_t)id * HH;
    const float* prow = pos + (size_t)s * HH;
    float* hrow = h + (size_t)row * HH;
    for (int i = threadIdx.x; i < HH; i += blockDim.x)
        hrow[i] = brow[i] + prow[i];
}

__global__ __launch_bounds__(256, 2)
void sgemm_kernel(const float* __restrict__ A, const float* __restrict__ B,
                  const float* __restrict__ bias, float* __restrict__ C,
                  int M, int N, int K, int gelu)
{
    __shared__ float As[8][128];
    __shared__ float Bs[8][128];

    int tid = threadIdx.x;
    int tx = tid & 15;
    int ty = tid >> 4;
    int row0 = blockIdx.y * 128;
    int col0 = blockIdx.x * 128;

    int aRow = tid >> 1;
    int aCol = (tid & 1) * 4;
    int bRow = tid >> 5;
    int bCol = (tid & 31) * 4;

    float acc[8][8];
#pragma unroll
    for (int i = 0; i < 8; i++)
#pragma unroll
        for (int j = 0; j < 8; j++) acc[i][j] = 0.f;

    const float* Aptr = A + (size_t)(row0 + aRow) * K + aCol;
    const float* Bptr = B + (size_t)bRow * N + col0 + bCol;

    for (int k0 = 0; k0 < K; k0 += 8) {
        float4 a4 = *(const float4*)(Aptr + k0);
        As[aCol + 0][aRow] = a4.x;
        As[aCol + 1][aRow] = a4.y;
        As[aCol + 2][aRow] = a4.z;
        As[aCol + 3][aRow] = a4.w;
        float4 b4 = *(const float4*)(Bptr + (size_t)k0 * N);
        *(float4*)&Bs[bRow][bCol] = b4;
        __syncthreads();
#pragma unroll
        for (int k = 0; k < 8; k++) {
            float ra[8], rb[8];
#pragma unroll
            for (int i = 0; i < 8; i++) ra[i] = As[k][ty * 8 + i];
#pragma unroll
            for (int j = 0; j < 8; j++) rb[j] = Bs[k][tx * 8 + j];
#pragma unroll
            for (int i = 0; i < 8; i++)
#pragma unroll
                for (int j = 0; j < 8; j++)
                    acc[i][j] = fmaf(ra[i], rb[j], acc[i][j]);
        }
        __syncthreads();
    }

#pragma unroll
    for (int i = 0; i < 8; i++) {
        int r = row0 + ty * 8 + i;
        float* crow = C + (size_t)r * N;
#pragma unroll
        for (int j = 0; j < 8; j += 4) {
            int c = col0 + tx * 8 + j;
            float4 v;
            v.x = acc[i][j + 0];
            v.y = acc[i][j + 1];
            v.z = acc[i][j + 2];
            v.w = acc[i][j + 3];
            if (bias) {
                v.x += bias[c + 0];
                v.y += bias[c + 1];
                v.z += bias[c + 2];
                v.w += bias[c + 3];
            }
            if (gelu) {
                v.x = 0.5f * v.x * (1.f + erff(v.x * 0.70710678118654752f));
                v.y = 0.5f * v.y * (1.f + erff(v.y * 0.70710678118654752f));
                v.z = 0.5f * v.z * (1.f + erff(v.z * 0.70710678118654752f));
                v.w = 0.5f * v.w * (1.f + erff(v.w * 0.70710678118654752f));
            }
            *(float4*)(crow + c) = v;
        }
    }
}

__global__ void attn_kernel(const float* __restrict__ qkv,
                            const float* __restrict__ seq_mask,
                            float* __restrict__ out)
{
    int q = blockIdx.x;
    int h = blockIdx.y;
    int b = blockIdx.z;
    int tid = threadIdx.x;

    __shared__ float qs[HD];
    __shared__ float sc[SS];
    __shared__ float red[128];

    if (tid < HD)
        qs[tid] = qkv[((size_t)(b * SS + q)) * TH + h * HD + tid];
    __syncthreads();

    float lmax = -3.0e38f;
    for (int j = tid; j < SS; j += 128) {
        float s;
        if (j <= q) {
            const float* krow = qkv + ((size_t)(b * SS + j)) * TH + HH + h * HD;
            float acc = 0.f;
#pragma unroll
            for (int d = 0; d < HD; d += 4) {
                float4 k4 = *(const float4*)(krow + d);
                acc += qs[d] * k4.x + qs[d + 1] * k4.y + qs[d + 2] * k4.z + qs[d + 3] * k4.w;
            }
            float m = seq_mask[b * SS + j];
            s = acc * 0.125f + (1.0f - m) * -1e9f;
        } else {
            s = -3.0e38f;
        }
        sc[j] = s;
        lmax = fmaxf(lmax, s);
    }
    red[tid] = lmax;
    __syncthreads();
    for (int off = 64; off > 0; off >>= 1) {
        if (tid < off) red[tid] = fmaxf(red[tid], red[tid + off]);
        __syncthreads();
    }
    float m = red[0];
    __syncthreads();

    float lsum = 0.f;
    for (int j = tid; j < SS; j += 128) {
        float e = (j <= q) ? expf(sc[j] - m) : 0.0f;
        sc[j] = e;
        lsum += e;
    }
    __syncthreads();
    red[tid] = lsum;
    __syncthreads();
    for (int off = 64; off > 0; off >>= 1) {
        if (tid < off) red[tid] += red[tid + off];
        __syncthreads();
    }
    float inv = 1.0f / red[0];

    if (tid < HD) {
        const float* vbase = qkv + ((size_t)(b * SS)) * TH + 2 * HH + h * HD + tid;
        float acc = 0.f;
        int j = 0;
        for (; j + 3 <= q; j += 4) {
            acc += sc[j + 0] * vbase[(size_t)(j + 0) * TH];
            acc += sc[j + 1] * vbase[(size_t)(j + 1) * TH];
            acc += sc[j + 2] * vbase[(size_t)(j + 2) * TH];
            acc += sc[j + 3] * vbase[(size_t)(j + 3) * TH];
        }
        for (; j <= q; j++)
            acc += sc[j] * vbase[(size_t)j * TH];
        out[((size_t)(b * SS + q)) * HH + h * HD + tid] = acc * inv;
    }
}

__global__ void add_ln_kernel(float* __restrict__ h, const float* __restrict__ a,
                              const float* __restrict__ g, const float* __restrict__ bt)
{
    int row = blockIdx.x;
    int tid = threadIdx.x;
    __shared__ float buf[HH];
    __shared__ float red[256];

    float* hrow = h + (size_t)row * HH;
    const float* arow = a + (size_t)row * HH;

    float lsum = 0.f;
#pragma unroll
    for (int i = 0; i < 3; i++) {
        int idx = tid + i * 256;
        float v = hrow[idx] + arow[idx];
        buf[idx] = v;
        lsum += v;
    }
    red[tid] = lsum;
    __syncthreads();
    for (int off = 128; off > 0; off >>= 1) {
        if (tid < off) red[tid] += red[tid + off];
        __syncthreads();
    }
    float mean = red[0] * (1.0f / HH);
    __syncthreads();

    float lvar = 0.f;
#pragma unroll
    for (int i = 0; i < 3; i++) {
        int idx = tid + i * 256;
        float d = buf[idx] - mean;
        lvar += d * d;
    }
    red[tid] = lvar;
    __syncthreads();
    for (int off = 128; off > 0; off >>= 1) {
        if (tid < off) red[tid] += red[tid + off];
        __syncthreads();
    }
    float rstd = rsqrtf(red[0] * (1.0f / HH) + 1e-5f);

#pragma unroll
    for (int i = 0; i < 3; i++) {
        int idx = tid + i * 256;
        hrow[idx] = g[idx] * ((buf[idx] - mean) * rstd) + bt[idx];
    }
}

__global__ void softmax_kernel(const float* __restrict__ x, float* __restrict__ p)
{
    int row = blockIdx.x;
    int tid = threadIdx.x;
    __shared__ float red[256];
    const float* xr = x + (size_t)row * VV;
    float* pr = p + (size_t)row * VV;

    float lmax = -3.0e38f;
    for (int i = tid; i < VV; i += 256) lmax = fmaxf(lmax, xr[i]);
    red[tid] = lmax;
    __syncthreads();
    for (int off = 128; off > 0; off >>= 1) {
        if (tid < off) red[tid] = fmaxf(red[tid], red[tid + off]);
        __syncthreads();
    }
    float m = red[0];
    __syncthreads();

    float lsum = 0.f;
    for (int i = tid; i < VV; i += 256) lsum += expf(xr[i] - m);
    red[tid] = lsum;
    __syncthreads();
    for (int off = 128; off > 0; off >>= 1) {
        if (tid < off) red[tid] += red[tid + off];
        __syncthreads();
    }
    float inv = 1.0f / red[0];

    for (int i = tid; i < VV; i += 256) pr[i] = expf(xr[i] - m) * inv;
}

extern "C" void kernel_launch(void* const* d_in, const int* in_sizes, int n_in,
                              void* d_out, int out_size)
{
    const int*   ids      = (const int*)d_in[0];
    const float* seq_mask = (const float*)d_in[1];
    const float* bpe      = (const float*)d_in[2];
    const float* pos      = (const float*)d_in[3];
    const float* qkv_w    = (const float*)d_in[4];
    const float* qkv_b    = (const float*)d_in[5];
    const float* res_w    = (const float*)d_in[6];
    const float* res_b    = (const float*)d_in[7];
    const float* ln1_g    = (const float*)d_in[8];
    const float* ln1_b    = (const float*)d_in[9];
    const float* ff1_w    = (const float*)d_in[10];
    const float* ff1_b    = (const float*)d_in[11];
    const float* ff2_w    = (const float*)d_in[12];
    const float* ff2_b    = (const float*)d_in[13];
    const float* ln2_g    = (const float*)d_in[14];
    const float* ln2_b    = (const float*)d_in[15];
    const float* pred_w   = (const float*)d_in[16];
    float* out = (float*)d_out;

    float *hP, *qkvP, *aP, *bP;
    cudaGetSymbolAddress((void**)&hP, g_h);
    cudaGetSymbolAddress((void**)&qkvP, g_qkv);
    cudaGetSymbolAddress((void**)&aP, g_a);
    cudaGetSymbolAddress((void**)&bP, g_b);

    embed_kernel<<<MM, 256>>>(ids, bpe, pos, hP);

    for (int l = 0; l < LL; l++) {
        sgemm_kernel<<<dim3(TH / 128, MM / 128), 256>>>(
            hP, qkv_w + (size_t)l * HH * TH, qkv_b + (size_t)l * TH,
            qkvP, MM, TH, HH, 0);

        attn_kernel<<<dim3(SS, NHD, BB), 128>>>(qkvP, seq_mask, aP);

        sgemm_kernel<<<dim3(HH / 128, MM / 128), 256>>>(
            aP, res_w + (size_t)l * HH * HH, res_b + (size_t)l * HH,
            bP, MM, HH, HH, 0);

        add_ln_kernel<<<MM, 256>>>(hP, bP, ln1_g + (size_t)l * HH, ln1_b + (size_t)l * HH);

        sgemm_kernel<<<dim3(4 * HH / 128, MM / 128), 256>>>(
            hP, ff1_w + (size_t)l * HH * 4 * HH, ff1_b + (size_t)l * 4 * HH,
            bP, MM, 4 * HH, HH, 1);

        sgemm_kernel<<<dim3(HH / 128, MM / 128), 256>>>(
            bP, ff2_w + (size_t)l * 4 * HH * HH, ff2_b + (size_t)l * HH,
            aP, MM, HH, 4 * HH, 0);

        add_ln_kernel<<<MM, 256>>>(hP, aP, ln2_g + (size_t)l * HH, ln2_b + (size_t)l * HH);
    }

    sgemm_kernel<<<dim3(VV / 128, MM / 128), 256>>>(
        hP, pred_w, nullptr, out, MM, VV, HH, 0);

    softmax_kernel<<<MM, 256>>>(out, out + (size_t)MM * VV);
}

// round 7
// speedup vs baseline: 1.4584x; 1.4584x over previous
#include <cuda_runtime.h>
#include <cuda_bf16.h>
#include <math.h>
#include <stdint.h>

#define BB 2
#define SS 1024
#define HH 768
#define NHD 12
#define HD 64
#define LL 4
#define VV 32000
#define MM (BB*SS)
#define TH (3*HH)

// ---------------- fp32 scratch -------------------------------------------------
__device__ float g_h[MM * HH];
__device__ float g_qkv[MM * TH];
__device__ float g_a[MM * HH];
__device__ float g_b[MM * 4 * HH];

// ---------------- augmented bf16 arenas ----------------------------------------
// Weights transposed to [N, 3K]: cols [0,K)=hi, [K,2K)=hi, [2K,3K)=lo
// Activations [M, 3K]:          cols [0,K)=hi, [K,2K)=lo, [2K,3K)=hi
#define QKV_SZ (2304*768)
#define RES_SZ (768*768)
#define FF1_SZ (3072*768)
#define FF2_SZ (768*3072)
#define PRED_SZ (32000*768)
#define OFF_QKV 0
#define OFF_RES (4*QKV_SZ)
#define OFF_FF1 (OFF_RES + 4*RES_SZ)
#define OFF_FF2 (OFF_FF1 + 4*FF1_SZ)
#define OFF_PRED (OFF_FF2 + 4*FF2_SZ)
#define WT_TOTAL (OFF_PRED + PRED_SZ)

__device__ unsigned short g_waug[(size_t)3 * WT_TOTAL];
__device__ unsigned short g_xaug[(size_t)MM * 3 * 4 * HH];

// ---------------- helpers -------------------------------------------------------
__device__ __forceinline__ uint32_t smem_u32(const void* p) {
    uint32_t a;
    asm("{ .reg .u64 t; cvta.to.shared.u64 t, %1; cvt.u32.u64 %0, t; }"
        : "=r"(a) : "l"(p));
    return a;
}
#define CP16(dst, src) \
    asm volatile("cp.async.cg.shared.global [%0], [%1], 16;" :: "r"(dst), "l"(src))
#define CP_COMMIT() asm volatile("cp.async.commit_group;" ::: "memory")
#define CP_WAIT1()  asm volatile("cp.async.wait_group 1;" ::: "memory")

__device__ __forceinline__ void ldm_x4(uint32_t* r, uint32_t addr) {
    asm volatile("ldmatrix.sync.aligned.m8n8.x4.shared.b16 {%0,%1,%2,%3}, [%4];"
                 : "=r"(r[0]), "=r"(r[1]), "=r"(r[2]), "=r"(r[3]) : "r"(addr));
}
__device__ __forceinline__ void mma16816(float* d, const uint32_t* a, const uint32_t* b) {
    asm volatile(
        "mma.sync.aligned.m16n8k16.row.col.f32.bf16.bf16.f32 "
        "{%0,%1,%2,%3}, {%4,%5,%6,%7}, {%8,%9}, {%0,%1,%2,%3};"
        : "+f"(d[0]), "+f"(d[1]), "+f"(d[2]), "+f"(d[3])
        : "r"(a[0]), "r"(a[1]), "r"(a[2]), "r"(a[3]), "r"(b[0]), "r"(b[1]));
}

// ---------------- conversion kernels -------------------------------------------
// x[M,K] fp32 -> Aaug[M,3K] bf16 (hi, lo, hi)
__global__ void conv_act_kernel(const float* __restrict__ x,
                                unsigned short* __restrict__ Aaug, int M, int K)
{
    int idx = blockIdx.x * blockDim.x + threadIdx.x;
    int kq4 = K >> 2;
    int m = idx / kq4;
    if (m >= M) return;
    int kq = idx - m * kq4;
    float4 v = ((const float4*)x)[idx];
    __nv_bfloat16 h0 = __float2bfloat16_rn(v.x);
    __nv_bfloat16 h1 = __float2bfloat16_rn(v.y);
    __nv_bfloat16 h2 = __float2bfloat16_rn(v.z);
    __nv_bfloat16 h3 = __float2bfloat16_rn(v.w);
    ushort4 hv, lv;
    hv.x = __bfloat16_as_ushort(h0); hv.y = __bfloat16_as_ushort(h1);
    hv.z = __bfloat16_as_ushort(h2); hv.w = __bfloat16_as_ushort(h3);
    lv.x = __bfloat16_as_ushort(__float2bfloat16_rn(v.x - __bfloat162float(h0)));
    lv.y = __bfloat16_as_ushort(__float2bfloat16_rn(v.y - __bfloat162float(h1)));
    lv.z = __bfloat16_as_ushort(__float2bfloat16_rn(v.z - __bfloat162float(h2)));
    lv.w = __bfloat16_as_ushort(__float2bfloat16_rn(v.w - __bfloat162float(h3)));
    size_t base = (size_t)m * 3 * K;
    ((ushort4*)(Aaug + base))[kq] = hv;
    ((ushort4*)(Aaug + base + K))[kq] = lv;
    ((ushort4*)(Aaug + base + 2 * K))[kq] = hv;
}

// W[K,N] fp32 -> Waug[N,3K] bf16 (hi, hi, lo), transposed
__global__ void wt_conv_kernel(const float* __restrict__ W,
                               unsigned short* __restrict__ Waug, int K, int N)
{
    __shared__ float t[32][33];
    int n0 = blockIdx.x * 32, k0 = blockIdx.y * 32;
    int tx = threadIdx.x, ty = threadIdx.y;   // 32 x 8
#pragma unroll
    for (int i = 0; i < 4; i++)
        t[ty + i * 8][tx] = W[(size_t)(k0 + ty + i * 8) * N + n0 + tx];
    __syncthreads();
    size_t K3 = (size_t)3 * K;
#pragma unroll
    for (int i = 0; i < 4; i++) {
        int n = n0 + ty + i * 8;
        int k = k0 + tx;
        float v = t[tx][ty + i * 8];
        __nv_bfloat16 h = __float2bfloat16_rn(v);
        unsigned short hu = __bfloat16_as_ushort(h);
        unsigned short lu = __bfloat16_as_ushort(__float2bfloat16_rn(v - __bfloat162float(h)));
        Waug[(size_t)n * K3 + k] = hu;
        Waug[(size_t)n * K3 + K + k] = hu;
        Waug[(size_t)n * K3 + 2 * K + k] = lu;
    }
}

// ---------------- bf16 HMMA GEMM: C[M,N] = Aaug[M,Ka] @ Baug[N,Ka]^T -----------
// 128x128 tile, BK=32, 3-stage cp.async, 8 warps (2x4), warp tile 64x32.
#define BKP 40                     // padded row stride in bf16 (80 bytes)
#define STG_BYTES (2 * 128 * BKP * 2)   // A tile + B tile per stage = 20480
#define GEMM_SMEM (3 * STG_BYTES)       // 61440

__global__ __launch_bounds__(256, 1)
void gemm_mma_kernel(const unsigned short* __restrict__ A,
                     const unsigned short* __restrict__ B,
                     const float* __restrict__ bias, float* __restrict__ C,
                     int M, int N, int Ka, int gelu)
{
    extern __shared__ char smem[];
    uint32_t sbase = smem_u32(smem);
    int tid = threadIdx.x;
    int wid = tid >> 5, lid = tid & 31;
    int row0 = blockIdx.y * 128, col0 = blockIdx.x * 128;
    int KT = Ka >> 5;

    // loader mapping: thread t copies 32B of row (t&127), half (t>>7)
    int lrow = tid & 127;
    int lhalf = tid >> 7;
    const char* gA = (const char*)(A + (size_t)(row0 + lrow) * Ka) + lhalf * 32;
    const char* gB = (const char*)(B + (size_t)(col0 + lrow) * Ka) + lhalf * 32;
    uint32_t sAw = sbase + lrow * 80 + lhalf * 32;
    uint32_t sBw = sbase + 128 * 80 + lrow * 80 + lhalf * 32;

    // prologue: stages 0,1
#pragma unroll
    for (int s = 0; s < 2; s++) {
        const char* pa = gA + (size_t)s * 64;
        const char* pb = gB + (size_t)s * 64;
        uint32_t da = sAw + s * STG_BYTES;
        uint32_t db = sBw + s * STG_BYTES;
        CP16(da, pa); CP16(da + 16, pa + 16);
        CP16(db, pb); CP16(db + 16, pb + 16);
        CP_COMMIT();
    }

    int wm0 = (wid >> 2) * 64;
    int wn0 = (wid & 3) * 32;

    // ldmatrix lane addresses (byte offsets within a stage)
    int a_r = ((lid >> 3) & 1) * 8 + (lid & 7);
    int a_k = ((lid >> 4) & 1) * 8;
    int b_r = ((lid >> 4) & 1) * 8 + (lid & 7);
    int b_k = ((lid >> 3) & 1) * 8;

    float acc[4][4][4];
#pragma unroll
    for (int i = 0; i < 4; i++)
#pragma unroll
        for (int j = 0; j < 4; j++)
#pragma unroll
            for (int q = 0; q < 4; q++) acc[i][j][q] = 0.f;

    for (int kt = 0; kt < KT; kt++) {
        CP_WAIT1();
        __syncthreads();
        // prefetch stage kt+2
        if (kt + 2 < KT) {
            int s = (kt + 2) % 3;
            const char* pa = gA + (size_t)(kt + 2) * 64;
            const char* pb = gB + (size_t)(kt + 2) * 64;
            uint32_t da = sAw + s * STG_BYTES;
            uint32_t db = sBw + s * STG_BYTES;
            CP16(da, pa); CP16(da + 16, pa + 16);
            CP16(db, pb); CP16(db + 16, pb + 16);
        }
        CP_COMMIT();

        uint32_t stA = sbase + (kt % 3) * STG_BYTES;
        uint32_t stB = stA + 128 * 80;
#pragma unroll
        for (int ks = 0; ks < 2; ks++) {
            uint32_t a[4][4];
#pragma unroll
            for (int mi = 0; mi < 4; mi++) {
                uint32_t addr = stA + (wm0 + mi * 16 + a_r) * 80 + (ks * 16 + a_k) * 2;
                ldm_x4(a[mi], addr);
            }
            uint32_t b[2][4];
#pragma unroll
            for (int pi = 0; pi < 2; pi++) {
                uint32_t addr = stB + (wn0 + pi * 16 + b_r) * 80 + (ks * 16 + b_k) * 2;
                ldm_x4(b[pi], addr);
            }
#pragma unroll
            for (int mi = 0; mi < 4; mi++) {
#pragma unroll
                for (int ni = 0; ni < 4; ni++) {
                    mma16816(acc[mi][ni], a[mi], &b[ni >> 1][(ni & 1) * 2]);
                }
            }
        }
    }

    // epilogue
    int qr = lid >> 2;          // 0..7
    int qc = (lid & 3) * 2;     // 0,2,4,6
#pragma unroll
    for (int mi = 0; mi < 4; mi++) {
#pragma unroll
        for (int ni = 0; ni < 4; ni++) {
            int col = col0 + wn0 + ni * 8 + qc;
            float b0 = 0.f, b1 = 0.f;
            if (bias) { b0 = bias[col]; b1 = bias[col + 1]; }
#pragma unroll
            for (int h = 0; h < 2; h++) {
                int row = row0 + wm0 + mi * 16 + qr + h * 8;
                float v0 = acc[mi][ni][h * 2 + 0] + b0;
                float v1 = acc[mi][ni][h * 2 + 1] + b1;
                if (gelu) {
                    v0 = 0.5f * v0 * (1.f + erff(v0 * 0.70710678118654752f));
                    v1 = 0.5f * v1 * (1.f + erff(v1 * 0.70710678118654752f));
                }
                float2 o; o.x = v0; o.y = v1;
                *(float2*)(C + (size_t)row * N + col) = o;
            }
        }
    }
}

// ---------------- embedding ----------------------------------------------------
__global__ void embed_kernel(const int* __restrict__ ids,
                             const float* __restrict__ bpe,
                             const float* __restrict__ pos,
                             float* __restrict__ h)
{
    int row = blockIdx.x;
    int s = row % SS;
    int id = ids[row];
    const float* brow = bpe + (size_t)id * HH;
    const float* prow = pos + (size_t)s * HH;
    float* hrow = h + (size_t)row * HH;
    for (int i = threadIdx.x; i < HH; i += blockDim.x)
        hrow[i] = brow[i] + prow[i];
}

// ---------------- attention ----------------------------------------------------
__global__ void attn_kernel(const float* __restrict__ qkv,
                            const float* __restrict__ seq_mask,
                            float* __restrict__ out)
{
    int q = blockIdx.x;
    int h = blockIdx.y;
    int b = blockIdx.z;
    int tid = threadIdx.x;

    __shared__ float qs[HD];
    __shared__ float sc[SS];
    __shared__ float red[128];

    if (tid < HD)
        qs[tid] = qkv[((size_t)(b * SS + q)) * TH + h * HD + tid];
    __syncthreads();

    float lmax = -3.0e38f;
    for (int j = tid; j < SS; j += 128) {
        float s;
        if (j <= q) {
            const float* krow = qkv + ((size_t)(b * SS + j)) * TH + HH + h * HD;
            float acc = 0.f;
#pragma unroll
            for (int d = 0; d < HD; d += 4) {
                float4 k4 = *(const float4*)(krow + d);
                acc += qs[d] * k4.x + qs[d + 1] * k4.y + qs[d + 2] * k4.z + qs[d + 3] * k4.w;
            }
            float m = seq_mask[b * SS + j];
            s = acc * 0.125f + (1.0f - m) * -1e9f;
        } else {
            s = -3.0e38f;
        }
        sc[j] = s;
        lmax = fmaxf(lmax, s);
    }
    red[tid] = lmax;
    __syncthreads();
    for (int off = 64; off > 0; off >>= 1) {
        if (tid < off) red[tid] = fmaxf(red[tid], red[tid + off]);
        __syncthreads();
    }
    float m = red[0];
    __syncthreads();

    float lsum = 0.f;
    for (int j = tid; j < SS; j += 128) {
        float e = (j <= q) ? expf(sc[j] - m) : 0.0f;
        sc[j] = e;
        lsum += e;
    }
    __syncthreads();
    red[tid] = lsum;
    __syncthreads();
    for (int off = 64; off > 0; off >>= 1) {
        if (tid < off) red[tid] += red[tid + off];
        __syncthreads();
    }
    float inv = 1.0f / red[0];

    if (tid < HD) {
        const float* vbase = qkv + ((size_t)(b * SS)) * TH + 2 * HH + h * HD + tid;
        float acc = 0.f;
        int j = 0;
        for (; j + 3 <= q; j += 4) {
            acc += sc[j + 0] * vbase[(size_t)(j + 0) * TH];
            acc += sc[j + 1] * vbase[(size_t)(j + 1) * TH];
            acc += sc[j + 2] * vbase[(size_t)(j + 2) * TH];
            acc += sc[j + 3] * vbase[(size_t)(j + 3) * TH];
        }
        for (; j <= q; j++)
            acc += sc[j] * vbase[(size_t)j * TH];
        out[((size_t)(b * SS + q)) * HH + h * HD + tid] = acc * inv;
    }
}

// ---------------- add + layernorm ----------------------------------------------
__global__ void add_ln_kernel(float* __restrict__ h, const float* __restrict__ a,
                              const float* __restrict__ g, const float* __restrict__ bt)
{
    int row = blockIdx.x;
    int tid = threadIdx.x;
    __shared__ float buf[HH];
    __shared__ float red[256];

    float* hrow = h + (size_t)row * HH;
    const float* arow = a + (size_t)row * HH;

    float lsum = 0.f;
#pragma unroll
    for (int i = 0; i < 3; i++) {
        int idx = tid + i * 256;
        float v = hrow[idx] + arow[idx];
        buf[idx] = v;
        lsum += v;
    }
    red[tid] = lsum;
    __syncthreads();
    for (int off = 128; off > 0; off >>= 1) {
        if (tid < off) red[tid] += red[tid + off];
        __syncthreads();
    }
    float mean = red[0] * (1.0f / HH);
    __syncthreads();

    float lvar = 0.f;
#pragma unroll
    for (int i = 0; i < 3; i++) {
        int idx = tid + i * 256;
        float d = buf[idx] - mean;
        lvar += d * d;
    }
    red[tid] = lvar;
    __syncthreads();
    for (int off = 128; off > 0; off >>= 1) {
        if (tid < off) red[tid] += red[tid + off];
        __syncthreads();
    }
    float rstd = rsqrtf(red[0] * (1.0f / HH) + 1e-5f);

#pragma unroll
    for (int i = 0; i < 3; i++) {
        int idx = tid + i * 256;
        hrow[idx] = g[idx] * ((buf[idx] - mean) * rstd) + bt[idx];
    }
}

// ---------------- vocab softmax -------------------------------------------------
__global__ void softmax_kernel(const float* __restrict__ x, float* __restrict__ p)
{
    int row = blockIdx.x;
    int tid = threadIdx.x;
    __shared__ float red[256];
    const float* xr = x + (size_t)row * VV;
    float* pr = p + (size_t)row * VV;

    float lmax = -3.0e38f;
    for (int i = tid; i < VV; i += 256) lmax = fmaxf(lmax, xr[i]);
    red[tid] = lmax;
    __syncthreads();
    for (int off = 128; off > 0; off >>= 1) {
        if (tid < off) red[tid] = fmaxf(red[tid], red[tid + off]);
        __syncthreads();
    }
    float m = red[0];
    __syncthreads();

    float lsum = 0.f;
    for (int i = tid; i < VV; i += 256) lsum += expf(xr[i] - m);
    red[tid] = lsum;
    __syncthreads();
    for (int off = 128; off > 0; off >>= 1) {
        if (tid < off) red[tid] += red[tid + off];
        __syncthreads();
    }
    float inv = 1.0f / red[0];

    for (int i = tid; i < VV; i += 256) pr[i] = expf(xr[i] - m) * inv;
}

// ---------------- launch --------------------------------------------------------
static void conv_act(const float* x, unsigned short* aug, int M, int K)
{
    int n = M * (K / 4);
    conv_act_kernel<<<(n + 255) / 256, 256>>>(x, aug, M, K);
}

extern "C" void kernel_launch(void* const* d_in, const int* in_sizes, int n_in,
                              void* d_out, int out_size)
{
    const int*   ids      = (const int*)d_in[0];
    const float* seq_mask = (const float*)d_in[1];
    const float* bpe      = (const float*)d_in[2];
    const float* pos      = (const float*)d_in[3];
    const float* qkv_w    = (const float*)d_in[4];
    const float* qkv_b    = (const float*)d_in[5];
    const float* res_w    = (const float*)d_in[6];
    const float* res_b    = (const float*)d_in[7];
    const float* ln1_g    = (const float*)d_in[8];
    const float* ln1_b    = (const float*)d_in[9];
    const float* ff1_w    = (const float*)d_in[10];
    const float* ff1_b    = (const float*)d_in[11];
    const float* ff2_w    = (const float*)d_in[12];
    const float* ff2_b    = (const float*)d_in[13];
    const float* ln2_g    = (const float*)d_in[14];
    const float* ln2_b    = (const float*)d_in[15];
    const float* pred_w   = (const float*)d_in[16];
    float* out = (float*)d_out;

    float *hP, *qkvP, *aP, *bP;
    unsigned short *waug, *xaug;
    cudaGetSymbolAddress((void**)&hP, g_h);
    cudaGetSymbolAddress((void**)&qkvP, g_qkv);
    cudaGetSymbolAddress((void**)&aP, g_a);
    cudaGetSymbolAddress((void**)&bP, g_b);
    cudaGetSymbolAddress((void**)&waug, g_waug);
    cudaGetSymbolAddress((void**)&xaug, g_xaug);

    cudaFuncSetAttribute(gemm_mma_kernel, cudaFuncAttributeMaxDynamicSharedMemorySize,
                         GEMM_SMEM);

    embed_kernel<<<MM, 256>>>(ids, bpe, pos, hP);

    // convert + transpose all weights into augmented [N, 3K] bf16
    for (int l = 0; l < LL; l++) {
        wt_conv_kernel<<<dim3(TH / 32, HH / 32), dim3(32, 8)>>>(
            qkv_w + (size_t)l * QKV_SZ, waug + (size_t)3 * (OFF_QKV + (size_t)l * QKV_SZ), HH, TH);
        wt_conv_kernel<<<dim3(HH / 32, HH / 32), dim3(32, 8)>>>(
            res_w + (size_t)l * RES_SZ, waug + (size_t)3 * (OFF_RES + (size_t)l * RES_SZ), HH, HH);
        wt_conv_kernel<<<dim3(4 * HH / 32, HH / 32), dim3(32, 8)>>>(
            ff1_w + (size_t)l * FF1_SZ, waug + (size_t)3 * (OFF_FF1 + (size_t)l * FF1_SZ), HH, 4 * HH);
        wt_conv_kernel<<<dim3(HH / 32, 4 * HH / 32), dim3(32, 8)>>>(
            ff2_w + (size_t)l * FF2_SZ, waug + (size_t)3 * (OFF_FF2 + (size_t)l * FF2_SZ), 4 * HH, HH);
    }
    wt_conv_kernel<<<dim3(VV / 32, HH / 32), dim3(32, 8)>>>(
        pred_w, waug + (size_t)3 * OFF_PRED, HH, VV);

    for (int l = 0; l < LL; l++) {
        // qkv: [2048,768] x [768,2304]
        conv_act(hP, xaug, MM, HH);
        gemm_mma_kernel<<<dim3(TH / 128, MM / 128), 256, GEMM_SMEM>>>(
            xaug, waug + (size_t)3 * (OFF_QKV + (size_t)l * QKV_SZ),
            qkv_b + (size_t)l * TH, qkvP, MM, TH, 3 * HH, 0);

        attn_kernel<<<dim3(SS, NHD, BB), 128>>>(qkvP, seq_mask, aP);

        // proj: [2048,768] x [768,768]
        conv_act(aP, xaug, MM, HH);
        gemm_mma_kernel<<<dim3(HH / 128, MM / 128), 256, GEMM_SMEM>>>(
            xaug, waug + (size_t)3 * (OFF_RES + (size_t)l * RES_SZ),
            res_b + (size_t)l * HH, bP, MM, HH, 3 * HH, 0);

        add_ln_kernel<<<MM, 256>>>(hP, bP, ln1_g + (size_t)l * HH, ln1_b + (size_t)l * HH);

        // ff1 + gelu: [2048,768] x [768,3072]
        conv_act(hP, xaug, MM, HH);
        gemm_mma_kernel<<<dim3(4 * HH / 128, MM / 128), 256, GEMM_SMEM>>>(
            xaug, waug + (size_t)3 * (OFF_FF1 + (size_t)l * FF1_SZ),
            ff1_b + (size_t)l * 4 * HH, bP, MM, 4 * HH, 3 * HH, 1);

        // ff2: [2048,3072] x [3072,768]
        conv_act(bP, xaug, MM, 4 * HH);
        gemm_mma_kernel<<<dim3(HH / 128, MM / 128), 256, GEMM_SMEM>>>(
            xaug, waug + (size_t)3 * (OFF_FF2 + (size_t)l * FF2_SZ),
            ff2_b + (size_t)l * HH, aP, MM, HH, 3 * 4 * HH, 0);

        add_ln_kernel<<<MM, 256>>>(hP, aP, ln2_g + (size_t)l * HH, ln2_b + (size_t)l * HH);
    }

    // logits: [2048,768] x [768,32000]
    conv_act(hP, xaug, MM, HH);
    gemm_mma_kernel<<<dim3(VV / 128, MM / 128), 256, GEMM_SMEM>>>(
        xaug, waug + (size_t)3 * OFF_PRED, nullptr, out, MM, VV, 3 * HH, 0);

    softmax_kernel<<<MM, 256>>>(out, out + (size_t)MM * VV);
}

// round 9
// speedup vs baseline: 2.5179x; 1.7265x over previous
#include <cuda_runtime.h>
#include <cuda_bf16.h>
#include <math.h>
#include <stdint.h>

#define BB 2
#define SS 1024
#define HH 768
#define NHD 12
#define HD 64
#define LL 4
#define VV 32000
#define MM (BB*SS)
#define TH (3*HH)

// ---------------- fp32 scratch -------------------------------------------------
__device__ float g_h[MM * HH];
__device__ float g_qkv[MM * TH];
__device__ float g_a[MM * HH];
__device__ float g_b[MM * 4 * HH];

// ---------------- augmented bf16 arenas ----------------------------------------
#define QKV_SZ (2304*768)
#define RES_SZ (768*768)
#define FF1_SZ (3072*768)
#define FF2_SZ (768*3072)
#define PRED_SZ (32000*768)
#define OFF_QKV 0
#define OFF_RES (4*QKV_SZ)
#define OFF_FF1 (OFF_RES + 4*RES_SZ)
#define OFF_FF2 (OFF_FF1 + 4*FF1_SZ)
#define OFF_PRED (OFF_FF2 + 4*FF2_SZ)
#define WT_TOTAL (OFF_PRED + PRED_SZ)

__device__ unsigned short g_waug[(size_t)3 * WT_TOTAL];
__device__ unsigned short g_xaug[(size_t)MM * 3 * 4 * HH];

// ---------------- helpers -------------------------------------------------------
__device__ __forceinline__ uint32_t smem_u32(const void* p) {
    uint32_t a;
    asm("{ .reg .u64 t; cvta.to.shared.u64 t, %1; cvt.u32.u64 %0, t; }"
        : "=r"(a) : "l"(p));
    return a;
}
#define CP16(dst, src) \
    asm volatile("cp.async.cg.shared.global [%0], [%1], 16;" :: "r"(dst), "l"(src))
#define CP_COMMIT() asm volatile("cp.async.commit_group;" ::: "memory")
#define CP_WAIT1()  asm volatile("cp.async.wait_group 1;" ::: "memory")

__device__ __forceinline__ void ldm_x4(uint32_t* r, uint32_t addr) {
    asm volatile("ldmatrix.sync.aligned.m8n8.x4.shared.b16 {%0,%1,%2,%3}, [%4];"
                 : "=r"(r[0]), "=r"(r[1]), "=r"(r[2]), "=r"(r[3]) : "r"(addr));
}
__device__ __forceinline__ void mma16816(float* d, const uint32_t* a, const uint32_t* b) {
    asm volatile(
        "mma.sync.aligned.m16n8k16.row.col.f32.bf16.bf16.f32 "
        "{%0,%1,%2,%3}, {%4,%5,%6,%7}, {%8,%9}, {%0,%1,%2,%3};"
        : "+f"(d[0]), "+f"(d[1]), "+f"(d[2]), "+f"(d[3])
        : "r"(a[0]), "r"(a[1]), "r"(a[2]), "r"(a[3]), "r"(b[0]), "r"(b[1]));
}

// ---------------- conversion kernels -------------------------------------------
__global__ void conv_act_kernel(const float* __restrict__ x,
                                unsigned short* __restrict__ Aaug, int M, int K)
{
    int idx = blockIdx.x * blockDim.x + threadIdx.x;
    int kq4 = K >> 2;
    int m = idx / kq4;
    if (m >= M) return;
    int kq = idx - m * kq4;
    float4 v = ((const float4*)x)[idx];
    __nv_bfloat16 h0 = __float2bfloat16_rn(v.x);
    __nv_bfloat16 h1 = __float2bfloat16_rn(v.y);
    __nv_bfloat16 h2 = __float2bfloat16_rn(v.z);
    __nv_bfloat16 h3 = __float2bfloat16_rn(v.w);
    ushort4 hv, lv;
    hv.x = __bfloat16_as_ushort(h0); hv.y = __bfloat16_as_ushort(h1);
    hv.z = __bfloat16_as_ushort(h2); hv.w = __bfloat16_as_ushort(h3);
    lv.x = __bfloat16_as_ushort(__float2bfloat16_rn(v.x - __bfloat162float(h0)));
    lv.y = __bfloat16_as_ushort(__float2bfloat16_rn(v.y - __bfloat162float(h1)));
    lv.z = __bfloat16_as_ushort(__float2bfloat16_rn(v.z - __bfloat162float(h2)));
    lv.w = __bfloat16_as_ushort(__float2bfloat16_rn(v.w - __bfloat162float(h3)));
    size_t base = (size_t)m * 3 * K;
    ((ushort4*)(Aaug + base))[kq] = hv;
    ((ushort4*)(Aaug + base + K))[kq] = lv;
    ((ushort4*)(Aaug + base + 2 * K))[kq] = hv;
}

__global__ void wt_conv_kernel(const float* __restrict__ W,
                               unsigned short* __restrict__ Waug, int K, int N)
{
    __shared__ float t[32][33];
    int n0 = blockIdx.x * 32, k0 = blockIdx.y * 32;
    int tx = threadIdx.x, ty = threadIdx.y;   // 32 x 8
#pragma unroll
    for (int i = 0; i < 4; i++)
        t[ty + i * 8][tx] = W[(size_t)(k0 + ty + i * 8) * N + n0 + tx];
    __syncthreads();
    size_t K3 = (size_t)3 * K;
#pragma unroll
    for (int i = 0; i < 4; i++) {
        int n = n0 + ty + i * 8;
        int k = k0 + tx;
        float v = t[tx][ty + i * 8];
        __nv_bfloat16 h = __float2bfloat16_rn(v);
        unsigned short hu = __bfloat16_as_ushort(h);
        unsigned short lu = __bfloat16_as_ushort(__float2bfloat16_rn(v - __bfloat162float(h)));
        Waug[(size_t)n * K3 + k] = hu;
        Waug[(size_t)n * K3 + K + k] = hu;
        Waug[(size_t)n * K3 + 2 * K + k] = lu;
    }
}

// ---------------- bf16 HMMA GEMM ------------------------------------------------
#define BKP 40
#define STG_BYTES (2 * 128 * BKP * 2)
#define GEMM_SMEM (3 * STG_BYTES)

__global__ __launch_bounds__(256, 2)
void gemm_mma_kernel(const unsigned short* __restrict__ A,
                     const unsigned short* __restrict__ B,
                     const float* __restrict__ bias, float* __restrict__ C,
                     int M, int N, int Ka, int gelu)
{
    extern __shared__ char smem[];
    uint32_t sbase = smem_u32(smem);
    int tid = threadIdx.x;
    int wid = tid >> 5, lid = tid & 31;
    int row0 = blockIdx.y * 128, col0 = blockIdx.x * 128;
    int KT = Ka >> 5;

    int lrow = tid & 127;
    int lhalf = tid >> 7;
    const char* gA = (const char*)(A + (size_t)(row0 + lrow) * Ka) + lhalf * 32;
    const char* gB = (const char*)(B + (size_t)(col0 + lrow) * Ka) + lhalf * 32;
    uint32_t sAw = sbase + lrow * 80 + lhalf * 32;
    uint32_t sBw = sbase + 128 * 80 + lrow * 80 + lhalf * 32;

#pragma unroll
    for (int s = 0; s < 2; s++) {
        const char* pa = gA + (size_t)s * 64;
        const char* pb = gB + (size_t)s * 64;
        uint32_t da = sAw + s * STG_BYTES;
        uint32_t db = sBw + s * STG_BYTES;
        CP16(da, pa); CP16(da + 16, pa + 16);
        CP16(db, pb); CP16(db + 16, pb + 16);
        CP_COMMIT();
    }

    int wm0 = (wid >> 2) * 64;
    int wn0 = (wid & 3) * 32;

    int a_r = ((lid >> 3) & 1) * 8 + (lid & 7);
    int a_k = ((lid >> 4) & 1) * 8;
    int b_r = ((lid >> 4) & 1) * 8 + (lid & 7);
    int b_k = ((lid >> 3) & 1) * 8;

    float acc[4][4][4];
#pragma unroll
    for (int i = 0; i < 4; i++)
#pragma unroll
        for (int j = 0; j < 4; j++)
#pragma unroll
            for (int q = 0; q < 4; q++) acc[i][j][q] = 0.f;

    for (int kt = 0; kt < KT; kt++) {
        CP_WAIT1();
        __syncthreads();
        if (kt + 2 < KT) {
            int s = (kt + 2) % 3;
            const char* pa = gA + (size_t)(kt + 2) * 64;
            const char* pb = gB + (size_t)(kt + 2) * 64;
            uint32_t da = sAw + s * STG_BYTES;
            uint32_t db = sBw + s * STG_BYTES;
            CP16(da, pa); CP16(da + 16, pa + 16);
            CP16(db, pb); CP16(db + 16, pb + 16);
        }
        CP_COMMIT();

        uint32_t stA = sbase + (kt % 3) * STG_BYTES;
        uint32_t stB = stA + 128 * 80;
#pragma unroll
        for (int ks = 0; ks < 2; ks++) {
            uint32_t a[4][4];
#pragma unroll
            for (int mi = 0; mi < 4; mi++) {
                uint32_t addr = stA + (wm0 + mi * 16 + a_r) * 80 + (ks * 16 + a_k) * 2;
                ldm_x4(a[mi], addr);
            }
            uint32_t b[2][4];
#pragma unroll
            for (int pi = 0; pi < 2; pi++) {
                uint32_t addr = stB + (wn0 + pi * 16 + b_r) * 80 + (ks * 16 + b_k) * 2;
                ldm_x4(b[pi], addr);
            }
#pragma unroll
            for (int mi = 0; mi < 4; mi++) {
#pragma unroll
                for (int ni = 0; ni < 4; ni++) {
                    mma16816(acc[mi][ni], a[mi], &b[ni >> 1][(ni & 1) * 2]);
                }
            }
        }
    }

    int qr = lid >> 2;
    int qc = (lid & 3) * 2;
#pragma unroll
    for (int mi = 0; mi < 4; mi++) {
#pragma unroll
        for (int ni = 0; ni < 4; ni++) {
            int col = col0 + wn0 + ni * 8 + qc;
            float b0 = 0.f, b1 = 0.f;
            if (bias) { b0 = bias[col]; b1 = bias[col + 1]; }
#pragma unroll
            for (int h = 0; h < 2; h++) {
                int row = row0 + wm0 + mi * 16 + qr + h * 8;
                float v0 = acc[mi][ni][h * 2 + 0] + b0;
                float v1 = acc[mi][ni][h * 2 + 1] + b1;
                if (gelu) {
                    v0 = 0.5f * v0 * (1.f + erff(v0 * 0.70710678118654752f));
                    v1 = 0.5f * v1 * (1.f + erff(v1 * 0.70710678118654752f));
                }
                float2 o; o.x = v0; o.y = v1;
                *(float2*)(C + (size_t)row * N + col) = o;
            }
        }
    }
}

// ---------------- embedding ----------------------------------------------------
__global__ void embed_kernel(const int* __restrict__ ids,
                             const float* __restrict__ bpe,
                             const float* __restrict__ pos,
                             float* __restrict__ h)
{
    int row = blockIdx.x;
    int s = row % SS;
    int id = ids[row];
    const float* brow = bpe + (size_t)id * HH;
    const float* prow = pos + (size_t)s * HH;
    float* hrow = h + (size_t)row * HH;
    for (int i = threadIdx.x; i < HH; i += blockDim.x)
        hrow[i] = brow[i] + prow[i];
}

// ---------------- tiled flash-style attention -----------------------------------
#define ATTN_SMEM ((4 * 4096 + 64) * 4)

__global__ __launch_bounds__(256, 2)
void attn_tile_kernel(const float* __restrict__ qkv,
                      const float* __restrict__ seq_mask,
                      float* __restrict__ out)
{
    extern __shared__ float smf[];
    float* Qt = smf;
    float* Kt = smf + 4096;
    float* Vs = smf + 8192;
    float* Pt = smf + 12288;
    float* msk = smf + 16384;

    int qt = blockIdx.x, h = blockIdx.y, b = blockIdx.z;
    int tid = threadIdx.x;
    int qg = tid >> 4;
    int lg = tid & 15;
    int q0 = qg * 4;
    int j0 = lg * 4;
    int tok_q0 = qt * 64;

#pragma unroll
    for (int i = 0; i < 4; i++) {
        int idx = tid + i * 256;
        int tk = idx >> 4;
        int d4 = (idx & 15) * 4;
        const float4 v = *(const float4*)(qkv + (size_t)(b * SS + tok_q0 + tk) * TH + h * HD + d4);
        Qt[(d4 + 0) * 64 + tk] = v.x;
        Qt[(d4 + 1) * 64 + tk] = v.y;
        Qt[(d4 + 2) * 64 + tk] = v.z;
        Qt[(d4 + 3) * 64 + tk] = v.w;
    }

    float O[4][4];
    float M[4], L[4];
#pragma unroll
    for (int qi = 0; qi < 4; qi++) {
        M[qi] = -1e30f; L[qi] = 0.f;
#pragma unroll
        for (int di = 0; di < 4; di++) O[qi][di] = 0.f;
    }

    for (int kt = 0; kt <= qt; kt++) {
        int tok_k0 = kt * 64;
        __syncthreads();
#pragma unroll
        for (int i = 0; i < 4; i++) {
            int idx = tid + i * 256;
            int tk = idx >> 4;
            int d4 = (idx & 15) * 4;
            const float* rowp = qkv + (size_t)(b * SS + tok_k0 + tk) * TH + h * HD;
            float4 kv = *(const float4*)(rowp + HH + d4);
            Kt[(d4 + 0) * 64 + tk] = kv.x;
            Kt[(d4 + 1) * 64 + tk] = kv.y;
            Kt[(d4 + 2) * 64 + tk] = kv.z;
            Kt[(d4 + 3) * 64 + tk] = kv.w;
            float4 vv = *(const float4*)(rowp + 2 * HH + d4);
            *(float4*)(Vs + tk * 64 + d4) = vv;
        }
        if (tid < 64) msk[tid] = seq_mask[b * SS + tok_k0 + tid];
        __syncthreads();

        float s[4][4];
#pragma unroll
        for (int qi = 0; qi < 4; qi++)
#pragma unroll
            for (int ji = 0; ji < 4; ji++) s[qi][ji] = 0.f;
        for (int d = 0; d < 64; d++) {
            const float4 qv = *(const float4*)(Qt + d * 64 + q0);
            const float4 kv = *(const float4*)(Kt + d * 64 + j0);
            float qa[4] = {qv.x, qv.y, qv.z, qv.w};
            float ka[4] = {kv.x, kv.y, kv.z, kv.w};
#pragma unroll
            for (int qi = 0; qi < 4; qi++)
#pragma unroll
                for (int ji = 0; ji < 4; ji++)
                    s[qi][ji] = fmaf(qa[qi], ka[ji], s[qi][ji]);
        }
#pragma unroll
        for (int qi = 0; qi < 4; qi++) {
            int gq = tok_q0 + q0 + qi;
#pragma unroll
            for (int ji = 0; ji < 4; ji++) {
                int gj = tok_k0 + j0 + ji;
                float v = s[qi][ji] * 0.125f + (1.0f - msk[j0 + ji]) * -1e9f;
                s[qi][ji] = (gj <= gq) ? v : -1e30f;
            }
        }
#pragma unroll
        for (int qi = 0; qi < 4; qi++) {
            float mt = fmaxf(fmaxf(s[qi][0], s[qi][1]), fmaxf(s[qi][2], s[qi][3]));
#pragma unroll
            for (int o = 1; o < 16; o <<= 1)
                mt = fmaxf(mt, __shfl_xor_sync(0xffffffffu, mt, o, 16));
            float Mn = fmaxf(M[qi], mt);
            float sc = expf(M[qi] - Mn);
            float ps = 0.f;
#pragma unroll
            for (int ji = 0; ji < 4; ji++) {
                float pv = expf(s[qi][ji] - Mn);
                s[qi][ji] = pv;
                ps += pv;
            }
            L[qi] = L[qi] * sc + ps;
#pragma unroll
            for (int di = 0; di < 4; di++) O[qi][di] *= sc;
            M[qi] = Mn;
        }
#pragma unroll
        for (int qi = 0; qi < 4; qi++)
#pragma unroll
            for (int ji = 0; ji < 4; ji++)
                Pt[(j0 + ji) * 64 + q0 + qi] = s[qi][ji];
        __syncthreads();

        int d0 = lg * 4;
        for (int j = 0; j < 64; j++) {
            const float4 pv = *(const float4*)(Pt + j * 64 + q0);
            const float4 vv = *(const float4*)(Vs + j * 64 + d0);
            float pa[4] = {pv.x, pv.y, pv.z, pv.w};
            float va[4] = {vv.x, vv.y, vv.z, vv.w};
#pragma unroll
            for (int qi = 0; qi < 4; qi++)
#pragma unroll
                for (int di = 0; di < 4; di++)
                    O[qi][di] = fmaf(pa[qi], va[di], O[qi][di]);
        }
    }

#pragma unroll
    for (int qi = 0; qi < 4; qi++) {
        float l = L[qi];
#pragma unroll
        for (int o = 1; o < 16; o <<= 1)
            l += __shfl_xor_sync(0xffffffffu, l, o, 16);
        float inv = 1.0f / l;
        float4 o4;
        o4.x = O[qi][0] * inv; o4.y = O[qi][1] * inv;
        o4.z = O[qi][2] * inv; o4.w = O[qi][3] * inv;
        *(float4*)(out + (size_t)(b * SS + tok_q0 + q0 + qi) * HH + h * HD + lg * 4) = o4;
    }
}

// ---------------- add + layernorm ----------------------------------------------
__global__ void add_ln_kernel(float* __restrict__ h, const float* __restrict__ a,
                              const float* __restrict__ g, const float* __restrict__ bt)
{
    int row = blockIdx.x;
    int tid = threadIdx.x;
    __shared__ float buf[HH];
    __shared__ float red[256];

    float* hrow = h + (size_t)row * HH;
    const float* arow = a + (size_t)row * HH;

    float lsum = 0.f;
#pragma unroll
    for (int i = 0; i < 3; i++) {
        int idx = tid + i * 256;
        float v = hrow[idx] + arow[idx];
        buf[idx] = v;
        lsum += v;
    }
    red[tid] = lsum;
    __syncthreads();
    for (int off = 128; off > 0; off >>= 1) {
        if (tid < off) red[tid] += red[tid + off];
        __syncthreads();
    }
    float mean = red[0] * (1.0f / HH);
    __syncthreads();

    float lvar = 0.f;
#pragma unroll
    for (int i = 0; i < 3; i++) {
        int idx = tid + i * 256;
        float d = buf[idx] - mean;
        lvar += d * d;
    }
    red[tid] = lvar;
    __syncthreads();
    for (int off = 128; off > 0; off >>= 1) {
        if (tid < off) red[tid] += red[tid + off];
        __syncthreads();
    }
    float rstd = rsqrtf(red[0] * (1.0f / HH) + 1e-5f);

#pragma unroll
    for (int i = 0; i < 3; i++) {
        int idx = tid + i * 256;
        hrow[idx] = g[idx] * ((buf[idx] - mean) * rstd) + bt[idx];
    }
}

// ---------------- vocab softmax (online max+sum, 2 read passes) -----------------
__global__ void softmax_kernel(const float* __restrict__ x, float* __restrict__ p)
{
    int row = blockIdx.x;
    int tid = threadIdx.x;
    __shared__ float rm[256], rl[256];
    const float* xr = x + (size_t)row * VV;
    float* pr = p + (size_t)row * VV;

    float m = -3.0e38f, l = 0.f;
    for (int i = tid; i < VV; i += 256) {
        float v = xr[i];
        if (v > m) { l = l * expf(m - v) + 1.0f; m = v; }
        else l += expf(v - m);
    }
    rm[tid] = m; rl[tid] = l;
    __syncthreads();
    for (int off = 128; off > 0; off >>= 1) {
        if (tid < off) {
            float m2 = rm[tid + off], l2 = rl[tid + off];
            float Mx = fmaxf(rm[tid], m2);
            rl[tid] = rl[tid] * expf(rm[tid] - Mx) + l2 * expf(m2 - Mx);
            rm[tid] = Mx;
        }
        __syncthreads();
    }
    float Mx = rm[0];
    float inv = 1.0f / rl[0];

    for (int i = tid; i < VV; i += 256) pr[i] = expf(xr[i] - Mx) * inv;
}

// ---------------- launch --------------------------------------------------------
static void conv_act(const float* x, unsigned short* aug, int M, int K)
{
    int n = M * (K / 4);
    conv_act_kernel<<<(n + 255) / 256, 256>>>(x, aug, M, K);
}

extern "C" void kernel_launch(void* const* d_in, const int* in_sizes, int n_in,
                              void* d_out, int out_size)
{
    const int*   ids      = (const int*)d_in[0];
    const float* seq_mask = (const float*)d_in[1];
    const float* bpe      = (const float*)d_in[2];
    const float* pos      = (const float*)d_in[3];
    const float* qkv_w    = (const float*)d_in[4];
    const float* qkv_b    = (const float*)d_in[5];
    const float* res_w    = (const float*)d_in[6];
    const float* res_b    = (const float*)d_in[7];
    const float* ln1_g    = (const float*)d_in[8];
    const float* ln1_b    = (const float*)d_in[9];
    const float* ff1_w    = (const float*)d_in[10];
    const float* ff1_b    = (const float*)d_in[11];
    const float* ff2_w    = (const float*)d_in[12];
    const float* ff2_b    = (const float*)d_in[13];
    const float* ln2_g    = (const float*)d_in[14];
    const float* ln2_b    = (const float*)d_in[15];
    const float* pred_w   = (const float*)d_in[16];
    float* out = (float*)d_out;

    float *hP, *qkvP, *aP, *bP;
    unsigned short *waug, *xaug;
    cudaGetSymbolAddress((void**)&hP, g_h);
    cudaGetSymbolAddress((void**)&qkvP, g_qkv);
    cudaGetSymbolAddress((void**)&aP, g_a);
    cudaGetSymbolAddress((void**)&bP, g_b);
    cudaGetSymbolAddress((void**)&waug, g_waug);
    cudaGetSymbolAddress((void**)&xaug, g_xaug);

    cudaFuncSetAttribute(gemm_mma_kernel, cudaFuncAttributeMaxDynamicSharedMemorySize,
                         GEMM_SMEM);
    cudaFuncSetAttribute(attn_tile_kernel, cudaFuncAttributeMaxDynamicSharedMemorySize,
                         ATTN_SMEM);

    embed_kernel<<<MM, 256>>>(ids, bpe, pos, hP);

    for (int l = 0; l < LL; l++) {
        wt_conv_kernel<<<dim3(TH / 32, HH / 32), dim3(32, 8)>>>(
            qkv_w + (size_t)l * QKV_SZ, waug + (size_t)3 * (OFF_QKV + (size_t)l * QKV_SZ), HH, TH);
        wt_conv_kernel<<<dim3(HH / 32, HH / 32), dim3(32, 8)>>>(
            res_w + (size_t)l * RES_SZ, waug + (size_t)3 * (OFF_RES + (size_t)l * RES_SZ), HH, HH);
        wt_conv_kernel<<<dim3(4 * HH / 32, HH / 32), dim3(32, 8)>>>(
            ff1_w + (size_t)l * FF1_SZ, waug + (size_t)3 * (OFF_FF1 + (size_t)l * FF1_SZ), HH, 4 * HH);
        wt_conv_kernel<<<dim3(HH / 32, 4 * HH / 32), dim3(32, 8)>>>(
            ff2_w + (size_t)l * FF2_SZ, waug + (size_t)3 * (OFF_FF2 + (size_t)l * FF2_SZ), 4 * HH, HH);
    }
    wt_conv_kernel<<<dim3(VV / 32, HH / 32), dim3(32, 8)>>>(
        pred_w, waug + (size_t)3 * OFF_PRED, HH, VV);

    for (int l = 0; l < LL; l++) {
        conv_act(hP, xaug, MM, HH);
        gemm_mma_kernel<<<dim3(TH / 128, MM / 128), 256, GEMM_SMEM>>>(
            xaug, waug + (size_t)3 * (OFF_QKV + (size_t)l * QKV_SZ),
            qkv_b + (size_t)l * TH, qkvP, MM, TH, 3 * HH, 0);

        attn_tile_kernel<<<dim3(SS / 64, NHD, BB), 256, ATTN_SMEM>>>(qkvP, seq_mask, aP);

        conv_act(aP, xaug, MM, HH);
        gemm_mma_kernel<<<dim3(HH / 128, MM / 128), 256, GEMM_SMEM>>>(
            xaug, waug + (size_t)3 * (OFF_RES + (size_t)l * RES_SZ),
            res_b + (size_t)l * HH, bP, MM, HH, 3 * HH, 0);

        add_ln_kernel<<<MM, 256>>>(hP, bP, ln1_g + (size_t)l * HH, ln1_b + (size_t)l * HH);

        conv_act(hP, xaug, MM, HH);
        gemm_mma_kernel<<<dim3(4 * HH / 128, MM / 128), 256, GEMM_SMEM>>>(
            xaug, waug + (size_t)3 * (OFF_FF1 + (size_t)l * FF1_SZ),
            ff1_b + (size_t)l * 4 * HH, bP, MM, 4 * HH, 3 * HH, 1);

        conv_act(bP, xaug, MM, 4 * HH);
        gemm_mma_kernel<<<dim3(HH / 128, MM / 128), 256, GEMM_SMEM>>>(
            xaug, waug + (size_t)3 * (OFF_FF2 + (size_t)l * FF2_SZ),
            ff2_b + (size_t)l * HH, aP, MM, HH, 3 * 4 * HH, 0);

        add_ln_kernel<<<MM, 256>>>(hP, aP, ln2_g + (size_t)l * HH, ln2_b + (size_t)l * HH);
    }

    conv_act(hP, xaug, MM, HH);
    gemm_mma_kernel<<<dim3(VV / 128, MM / 128), 256, GEMM_SMEM>>>(
        xaug, waug + (size_t)3 * OFF_PRED, nullptr, out, MM, VV, 3 * HH, 0);

    softmax_kernel<<<MM, 256>>>(out, out + (size_t)MM * VV);
}

// round 12
// speedup vs baseline: 2.5382x; 1.0080x over previous
#include <cuda_runtime.h>
#include <cuda_bf16.h>
#include <math.h>
#include <stdint.h>

#define BB 2
#define SS 1024
#define HH 768
#define NHD 12
#define HD 64
#define LL 4
#define VV 32000
#define MM (BB*SS)
#define TH (3*HH)

// ---------------- fp32 scratch -------------------------------------------------
__device__ float g_h[MM * HH];
__device__ float g_qkv[MM * TH];
__device__ float g_a[MM * HH];
__device__ float g_b[MM * HH];

// ---------------- augmented bf16 arenas ----------------------------------------
#define QKV_SZ (2304*768)
#define RES_SZ (768*768)
#define FF1_SZ (3072*768)
#define FF2_SZ (768*3072)
#define PRED_SZ (32000*768)
#define OFF_QKV 0
#define OFF_RES (4*QKV_SZ)
#define OFF_FF1 (OFF_RES + 4*RES_SZ)
#define OFF_FF2 (OFF_FF1 + 4*FF1_SZ)
#define OFF_PRED (OFF_FF2 + 4*FF2_SZ)
#define WT_TOTAL (OFF_PRED + PRED_SZ)

__device__ unsigned short g_waug[(size_t)3 * WT_TOTAL];
__device__ unsigned short g_augN[(size_t)MM * 3 * HH];      // narrow act aug (K=768)
__device__ unsigned short g_augW[(size_t)MM * 3 * 4 * HH];  // wide act aug (K=3072)

// ---------------- helpers -------------------------------------------------------
__device__ __forceinline__ uint32_t smem_u32(const void* p) {
    uint32_t a;
    asm("{ .reg .u64 t; cvta.to.shared.u64 t, %1; cvt.u32.u64 %0, t; }"
        : "=r"(a) : "l"(p));
    return a;
}
#define CP16(dst, src) \
    asm volatile("cp.async.cg.shared.global [%0], [%1], 16;" :: "r"(dst), "l"(src))
#define CP_COMMIT() asm volatile("cp.async.commit_group;" ::: "memory")
#define CP_WAIT1()  asm volatile("cp.async.wait_group 1;" ::: "memory")

__device__ __forceinline__ void ldm_x4(uint32_t* r, uint32_t addr) {
    asm volatile("ldmatrix.sync.aligned.m8n8.x4.shared.b16 {%0,%1,%2,%3}, [%4];"
                 : "=r"(r[0]), "=r"(r[1]), "=r"(r[2]), "=r"(r[3]) : "r"(addr));
}
__device__ __forceinline__ void mma16816(float* d, const uint32_t* a, const uint32_t* b) {
    asm volatile(
        "mma.sync.aligned.m16n8k16.row.col.f32.bf16.bf16.f32 "
        "{%0,%1,%2,%3}, {%4,%5,%6,%7}, {%8,%9}, {%0,%1,%2,%3};"
        : "+f"(d[0]), "+f"(d[1]), "+f"(d[2]), "+f"(d[3])
        : "r"(a[0]), "r"(a[1]), "r"(a[2]), "r"(a[3]), "r"(b[0]), "r"(b[1]));
}
__device__ __forceinline__ void split_bf16(float v, unsigned short& hi, unsigned short& lo) {
    __nv_bfloat16 h = __float2bfloat16_rn(v);
    hi = __bfloat16_as_ushort(h);
    lo = __bfloat16_as_ushort(__float2bfloat16_rn(v - __bfloat162float(h)));
}

// ---------------- weight conversion ---------------------------------------------
__global__ void wt_conv_kernel(const float* __restrict__ W,
                               unsigned short* __restrict__ Waug, int K, int N)
{
    __shared__ float t[32][33];
    int n0 = blockIdx.x * 32, k0 = blockIdx.y * 32;
    int tx = threadIdx.x, ty = threadIdx.y;
#pragma unroll
    for (int i = 0; i < 4; i++)
        t[ty + i * 8][tx] = W[(size_t)(k0 + ty + i * 8) * N + n0 + tx];
    __syncthreads();
    size_t K3 = (size_t)3 * K;
#pragma unroll
    for (int i = 0; i < 4; i++) {
        int n = n0 + ty + i * 8;
        int k = k0 + tx;
        float v = t[tx][ty + i * 8];
        unsigned short hu, lu;
        split_bf16(v, hu, lu);
        Waug[(size_t)n * K3 + k] = hu;
        Waug[(size_t)n * K3 + K + k] = hu;
        Waug[(size_t)n * K3 + 2 * K + k] = lu;
    }
}

// ---------------- bf16 HMMA GEMM ------------------------------------------------
#define BKP 40
#define STG_BYTES (2 * 128 * BKP * 2)
#define GEMM_SMEM (3 * STG_BYTES)

__global__ __launch_bounds__(256, 2)
void gemm_mma_kernel(const unsigned short* __restrict__ A,
                     const unsigned short* __restrict__ B,
                     const float* __restrict__ bias, float* __restrict__ C,
                     unsigned short* __restrict__ Caug,
                     int M, int N, int Ka, int gelu)
{
    extern __shared__ char smem[];
    uint32_t sbase = smem_u32(smem);
    int tid = threadIdx.x;
    int wid = tid >> 5, lid = tid & 31;
    int row0 = blockIdx.y * 128, col0 = blockIdx.x * 128;
    int KT = Ka >> 5;

    int lrow = tid & 127;
    int lhalf = tid >> 7;
    const char* gA = (const char*)(A + (size_t)(row0 + lrow) * Ka) + lhalf * 32;
    const char* gB = (const char*)(B + (size_t)(col0 + lrow) * Ka) + lhalf * 32;
    uint32_t sAw = sbase + lrow * 80 + lhalf * 32;
    uint32_t sBw = sbase + 128 * 80 + lrow * 80 + lhalf * 32;

#pragma unroll
    for (int s = 0; s < 2; s++) {
        const char* pa = gA + (size_t)s * 64;
        const char* pb = gB + (size_t)s * 64;
        uint32_t da = sAw + s * STG_BYTES;
        uint32_t db = sBw + s * STG_BYTES;
        CP16(da, pa); CP16(da + 16, pa + 16);
        CP16(db, pb); CP16(db + 16, pb + 16);
        CP_COMMIT();
    }

    int wm0 = (wid >> 2) * 64;
    int wn0 = (wid & 3) * 32;

    int a_r = ((lid >> 3) & 1) * 8 + (lid & 7);
    int a_k = ((lid >> 4) & 1) * 8;
    int b_r = ((lid >> 4) & 1) * 8 + (lid & 7);
    int b_k = ((lid >> 3) & 1) * 8;

    float acc[4][4][4];
#pragma unroll
    for (int i = 0; i < 4; i++)
#pragma unroll
        for (int j = 0; j < 4; j++)
#pragma unroll
            for (int q = 0; q < 4; q++) acc[i][j][q] = 0.f;

    for (int kt = 0; kt < KT; kt++) {
        CP_WAIT1();
        __syncthreads();
        if (kt + 2 < KT) {
            int s = (kt + 2) % 3;
            const char* pa = gA + (size_t)(kt + 2) * 64;
            const char* pb = gB + (size_t)(kt + 2) * 64;
            uint32_t da = sAw + s * STG_BYTES;
            uint32_t db = sBw + s * STG_BYTES;
            CP16(da, pa); CP16(da + 16, pa + 16);
            CP16(db, pb); CP16(db + 16, pb + 16);
        }
        CP_COMMIT();

        uint32_t stA = sbase + (kt % 3) * STG_BYTES;
        uint32_t stB = stA + 128 * 80;
#pragma unroll
        for (int ks = 0; ks < 2; ks++) {
            uint32_t a[4][4];
#pragma unroll
            for (int mi = 0; mi < 4; mi++) {
                uint32_t addr = stA + (wm0 + mi * 16 + a_r) * 80 + (ks * 16 + a_k) * 2;
                ldm_x4(a[mi], addr);
            }
            uint32_t b[2][4];
#pragma unroll
            for (int pi = 0; pi < 2; pi++) {
                uint32_t addr = stB + (wn0 + pi * 16 + b_r) * 80 + (ks * 16 + b_k) * 2;
                ldm_x4(b[pi], addr);
            }
#pragma unroll
            for (int mi = 0; mi < 4; mi++) {
#pragma unroll
                for (int ni = 0; ni < 4; ni++) {
                    mma16816(acc[mi][ni], a[mi], &b[ni >> 1][(ni & 1) * 2]);
                }
            }
        }
    }

    int qr = lid >> 2;
    int qc = (lid & 3) * 2;
    size_t N3 = (size_t)3 * N;
#pragma unroll
    for (int mi = 0; mi < 4; mi++) {
#pragma unroll
        for (int ni = 0; ni < 4; ni++) {
            int col = col0 + wn0 + ni * 8 + qc;
            float b0 = 0.f, b1 = 0.f;
            if (bias) { b0 = bias[col]; b1 = bias[col + 1]; }
#pragma unroll
            for (int h = 0; h < 2; h++) {
                int row = row0 + wm0 + mi * 16 + qr + h * 8;
                float v0 = acc[mi][ni][h * 2 + 0] + b0;
                float v1 = acc[mi][ni][h * 2 + 1] + b1;
                if (gelu) {
                    v0 = 0.5f * v0 * (1.f + erff(v0 * 0.70710678118654752f));
                    v1 = 0.5f * v1 * (1.f + erff(v1 * 0.70710678118654752f));
                }
                if (C) {
                    float2 o; o.x = v0; o.y = v1;
                    *(float2*)(C + (size_t)row * N + col) = o;
                }
                if (Caug) {
                    unsigned short h0, l0, h1, l1;
                    split_bf16(v0, h0, l0);
                    split_bf16(v1, h1, l1);
                    unsigned short* base = Caug + (size_t)row * N3 + col;
                    ushort2 hv; hv.x = h0; hv.y = h1;
                    ushort2 lv; lv.x = l0; lv.y = l1;
                    *(ushort2*)(base) = hv;
                    *(ushort2*)(base + N) = lv;
                    *(ushort2*)(base + 2 * N) = hv;
                }
            }
        }
    }
}

// ---------------- embedding (writes h fp32 + narrow aug) ------------------------
__global__ void embed_kernel(const int* __restrict__ ids,
                             const float* __restrict__ bpe,
                             const float* __restrict__ pos,
                             float* __restrict__ h,
                             unsigned short* __restrict__ aug)
{
    int row = blockIdx.x;
    int s = row % SS;
    int id = ids[row];
    const float* brow = bpe + (size_t)id * HH;
    const float* prow = pos + (size_t)s * HH;
    float* hrow = h + (size_t)row * HH;
    unsigned short* arow = aug + (size_t)row * 3 * HH;
    for (int i = threadIdx.x; i < HH; i += blockDim.x) {
        float v = brow[i] + prow[i];
        hrow[i] = v;
        unsigned short hu, lu;
        split_bf16(v, hu, lu);
        arow[i] = hu;
        arow[HH + i] = lu;
        arow[2 * HH + i] = hu;
    }
}

// ---------------- tiled flash-style attention (writes narrow aug directly) ------
#define ATTN_SMEM ((4 * 4096 + 64) * 4)

__global__ __launch_bounds__(256, 2)
void attn_tile_kernel(const float* __restrict__ qkv,
                      const float* __restrict__ seq_mask,
                      unsigned short* __restrict__ outaug)
{
    extern __shared__ float smf[];
    float* Qt = smf;
    float* Kt = smf + 4096;
    float* Vs = smf + 8192;
    float* Pt = smf + 12288;
    float* msk = smf + 16384;

    int qt = blockIdx.x, h = blockIdx.y, b = blockIdx.z;
    int tid = threadIdx.x;
    int qg = tid >> 4;
    int lg = tid & 15;
    int q0 = qg * 4;
    int j0 = lg * 4;
    int tok_q0 = qt * 64;

#pragma unroll
    for (int i = 0; i < 4; i++) {
        int idx = tid + i * 256;
        int tk = idx >> 4;
        int d4 = (idx & 15) * 4;
        const float4 v = *(const float4*)(qkv + (size_t)(b * SS + tok_q0 + tk) * TH + h * HD + d4);
        Qt[(d4 + 0) * 64 + tk] = v.x;
        Qt[(d4 + 1) * 64 + tk] = v.y;
        Qt[(d4 + 2) * 64 + tk] = v.z;
        Qt[(d4 + 3) * 64 + tk] = v.w;
    }

    float O[4][4];
    float M[4], L[4];
#pragma unroll
    for (int qi = 0; qi < 4; qi++) {
        M[qi] = -1e30f; L[qi] = 0.f;
#pragma unroll
        for (int di = 0; di < 4; di++) O[qi][di] = 0.f;
    }

    for (int kt = 0; kt <= qt; kt++) {
        int tok_k0 = kt * 64;
        __syncthreads();
#pragma unroll
        for (int i = 0; i < 4; i++) {
            int idx = tid + i * 256;
            int tk = idx >> 4;
            int d4 = (idx & 15) * 4;
            const float* rowp = qkv + (size_t)(b * SS + tok_k0 + tk) * TH + h * HD;
            float4 kv = *(const float4*)(rowp + HH + d4);
            Kt[(d4 + 0) * 64 + tk] = kv.x;
            Kt[(d4 + 1) * 64 + tk] = kv.y;
            Kt[(d4 + 2) * 64 + tk] = kv.z;
            Kt[(d4 + 3) * 64 + tk] = kv.w;
            float4 vv = *(const float4*)(rowp + 2 * HH + d4);
            *(float4*)(Vs + tk * 64 + d4) = vv;
        }
        if (tid < 64) msk[tid] = seq_mask[b * SS + tok_k0 + tid];
        __syncthreads();

        float s[4][4];
#pragma unroll
        for (int qi = 0; qi < 4; qi++)
#pragma unroll
            for (int ji = 0; ji < 4; ji++) s[qi][ji] = 0.f;
        for (int d = 0; d < 64; d++) {
            const float4 qv = *(const float4*)(Qt + d * 64 + q0);
            const float4 kv = *(const float4*)(Kt + d * 64 + j0);
            float qa[4] = {qv.x, qv.y, qv.z, qv.w};
            float ka[4] = {kv.x, kv.y, kv.z, kv.w};
#pragma unroll
            for (int qi = 0; qi < 4; qi++)
#pragma unroll
                for (int ji = 0; ji < 4; ji++)
                    s[qi][ji] = fmaf(qa[qi], ka[ji], s[qi][ji]);
        }
#pragma unroll
        for (int qi = 0; qi < 4; qi++) {
            int gq = tok_q0 + q0 + qi;
#pragma unroll
            for (int ji = 0; ji < 4; ji++) {
                int gj = tok_k0 + j0 + ji;
                float v = s[qi][ji] * 0.125f + (1.0f - msk[j0 + ji]) * -1e9f;
                s[qi][ji] = (gj <= gq) ? v : -1e30f;
            }
        }
#pragma unroll
        for (int qi = 0; qi < 4; qi++) {
            float mt = fmaxf(fmaxf(s[qi][0], s[qi][1]), fmaxf(s[qi][2], s[qi][3]));
#pragma unroll
            for (int o = 1; o < 16; o <<= 1)
                mt = fmaxf(mt, __shfl_xor_sync(0xffffffffu, mt, o, 16));
            float Mn = fmaxf(M[qi], mt);
            float sc = expf(M[qi] - Mn);
            float ps = 0.f;
#pragma unroll
            for (int ji = 0; ji < 4; ji++) {
                float pv = expf(s[qi][ji] - Mn);
                s[qi][ji] = pv;
                ps += pv;
            }
            L[qi] = L[qi] * sc + ps;
#pragma unroll
            for (int di = 0; di < 4; di++) O[qi][di] *= sc;
            M[qi] = Mn;
        }
#pragma unroll
        for (int qi = 0; qi < 4; qi++)
#pragma unroll
            for (int ji = 0; ji < 4; ji++)
                Pt[(j0 + ji) * 64 + q0 + qi] = s[qi][ji];
        __syncthreads();

        int d0 = lg * 4;
        for (int j = 0; j < 64; j++) {
            const float4 pv = *(const float4*)(Pt + j * 64 + q0);
            const float4 vv = *(const float4*)(Vs + j * 64 + d0);
            float pa[4] = {pv.x, pv.y, pv.z, pv.w};
            float va[4] = {vv.x, vv.y, vv.z, vv.w};
#pragma unroll
            for (int qi = 0; qi < 4; qi++)
#pragma unroll
                for (int di = 0; di < 4; di++)
                    O[qi][di] = fmaf(pa[qi], va[di], O[qi][di]);
        }
    }

#pragma unroll
    for (int qi = 0; qi < 4; qi++) {
        float l = L[qi];
#pragma unroll
        for (int o = 1; o < 16; o <<= 1)
            l += __shfl_xor_sync(0xffffffffu, l, o, 16);
        float inv = 1.0f / l;
        int col = h * HD + lg * 4;
        unsigned short* base = outaug + (size_t)(b * SS + tok_q0 + q0 + qi) * 3 * HH + col;
        ushort4 hv, lv;
        unsigned short hu, lu;
        split_bf16(O[qi][0] * inv, hu, lu); hv.x = hu; lv.x = lu;
        split_bf16(O[qi][1] * inv, hu, lu); hv.y = hu; lv.y = lu;
        split_bf16(O[qi][2] * inv, hu, lu); hv.z = hu; lv.z = lu;
        split_bf16(O[qi][3] * inv, hu, lu); hv.w = hu; lv.w = lu;
        *(ushort4*)(base) = hv;
        *(ushort4*)(base + HH) = lv;
        *(ushort4*)(base + 2 * HH) = hv;
    }
}

// ---------------- add + layernorm (writes h fp32 + narrow aug) -------------------
__global__ void add_ln_kernel(float* __restrict__ h, const float* __restrict__ a,
                              const float* __restrict__ g, const float* __restrict__ bt,
                              unsigned short* __restrict__ aug)
{
    int row = blockIdx.x;
    int tid = threadIdx.x;
    __shared__ float buf[HH];
    __shared__ float red[256];

    float* hrow = h + (size_t)row * HH;
    const float* arow = a + (size_t)row * HH;
    unsigned short* grow = aug + (size_t)row * 3 * HH;

    float lsum = 0.f;
#pragma unroll
    for (int i = 0; i < 3; i++) {
        int idx = tid + i * 256;
        float v = hrow[idx] + arow[idx];
        buf[idx] = v;
        lsum += v;
    }
    red[tid] = lsum;
    __syncthreads();
    for (int off = 128; off > 0; off >>= 1) {
        if (tid < off) red[tid] += red[tid + off];
        __syncthreads();
    }
    float mean = red[0] * (1.0f / HH);
    __syncthreads();

    float lvar = 0.f;
#pragma unroll
    for (int i = 0; i < 3; i++) {
        int idx = tid + i * 256;
        float d = buf[idx] - mean;
        lvar += d * d;
    }
    red[tid] = lvar;
    __syncthreads();
    for (int off = 128; off > 0; off >>= 1) {
        if (tid < off) red[tid] += red[tid + off];
        __syncthreads();
    }
    float rstd = rsqrtf(red[0] * (1.0f / HH) + 1e-5f);

#pragma unroll
    for (int i = 0; i < 3; i++) {
        int idx = tid + i * 256;
        float y = g[idx] * ((buf[idx] - mean) * rstd) + bt[idx];
        hrow[idx] = y;
        unsigned short hu, lu;
        split_bf16(y, hu, lu);
        grow[idx] = hu;
        grow[HH + idx] = lu;
        grow[2 * HH + idx] = hu;
    }
}

// ---------------- vocab softmax (online) -----------------------------------------
__global__ void softmax_kernel(const float* __restrict__ x, float* __restrict__ p)
{
    int row = blockIdx.x;
    int tid = threadIdx.x;
    __shared__ float rm[256], rl[256];
    const float* xr = x + (size_t)row * VV;
    float* pr = p + (size_t)row * VV;

    float m = -3.0e38f, l = 0.f;
    for (int i = tid; i < VV; i += 256) {
        float v = xr[i];
        if (v > m) { l = l * expf(m - v) + 1.0f; m = v; }
        else l += expf(v - m);
    }
    rm[tid] = m; rl[tid] = l;
    __syncthreads();
    for (int off = 128; off > 0; off >>= 1) {
        if (tid < off) {
            float m2 = rm[tid + off], l2 = rl[tid + off];
            float Mx = fmaxf(rm[tid], m2);
            rl[tid] = rl[tid] * expf(rm[tid] - Mx) + l2 * expf(m2 - Mx);
            rm[tid] = Mx;
        }
        __syncthreads();
    }
    float Mx = rm[0];
    float inv = 1.0f / rl[0];

    for (int i = tid; i < VV; i += 256) pr[i] = expf(xr[i] - Mx) * inv;
}

// ---------------- launch --------------------------------------------------------
extern "C" void kernel_launch(void* const* d_in, const int* in_sizes, int n_in,
                              void* d_out, int out_size)
{
    const int*   ids      = (const int*)d_in[0];
    const float* seq_mask = (const float*)d_in[1];
    const float* bpe      = (const float*)d_in[2];
    const float* pos      = (const float*)d_in[3];
    const float* qkv_w    = (const float*)d_in[4];
    const float* qkv_b    = (const float*)d_in[5];
    const float* res_w    = (const float*)d_in[6];
    const float* res_b    = (const float*)d_in[7];
    const float* ln1_g    = (const float*)d_in[8];
    const float* ln1_b    = (const float*)d_in[9];
    const float* ff1_w    = (const float*)d_in[10];
    const float* ff1_b    = (const float*)d_in[11];
    const float* ff2_w    = (const float*)d_in[12];
    const float* ff2_b    = (const float*)d_in[13];
    const float* ln2_g    = (const float*)d_in[14];
    const float* ln2_b    = (const float*)d_in[15];
    const float* pred_w   = (const float*)d_in[16];
    float* out = (float*)d_out;

    float *hP, *qkvP, *aP, *bP;
    unsigned short *waug, *augN, *augW;
    cudaGetSymbolAddress((void**)&hP, g_h);
    cudaGetSymbolAddress((void**)&qkvP, g_qkv);
    cudaGetSymbolAddress((void**)&aP, g_a);
    cudaGetSymbolAddress((void**)&bP, g_b);
    cudaGetSymbolAddress((void**)&waug, g_waug);
    cudaGetSymbolAddress((void**)&augN, g_augN);
    cudaGetSymbolAddress((void**)&augW, g_augW);

    cudaFuncSetAttribute(gemm_mma_kernel, cudaFuncAttributeMaxDynamicSharedMemorySize,
                         GEMM_SMEM);
    cudaFuncSetAttribute(attn_tile_kernel, cudaFuncAttributeMaxDynamicSharedMemorySize,
                         ATTN_SMEM);

    embed_kernel<<<MM, 256>>>(ids, bpe, pos, hP, augN);

    for (int l = 0; l < LL; l++) {
        wt_conv_kernel<<<dim3(TH / 32, HH / 32), dim3(32, 8)>>>(
            qkv_w + (size_t)l * QKV_SZ, waug + (size_t)3 * (OFF_QKV + (size_t)l * QKV_SZ), HH, TH);
        wt_conv_kernel<<<dim3(HH / 32, HH / 32), dim3(32, 8)>>>(
            res_w + (size_t)l * RES_SZ, waug + (size_t)3 * (OFF_RES + (size_t)l * RES_SZ), HH, HH);
        wt_conv_kernel<<<dim3(4 * HH / 32, HH / 32), dim3(32, 8)>>>(
            ff1_w + (size_t)l * FF1_SZ, waug + (size_t)3 * (OFF_FF1 + (size_t)l * FF1_SZ), HH, 4 * HH);
        wt_conv_kernel<<<dim3(HH / 32, 4 * HH / 32), dim3(32, 8)>>>(
            ff2_w + (size_t)l * FF2_SZ, waug + (size_t)3 * (OFF_FF2 + (size_t)l * FF2_SZ), 4 * HH, HH);

        gemm_mma_kernel<<<dim3(TH / 128, MM / 128), 256, GEMM_SMEM>>>(
            augN, waug + (size_t)3 * (OFF_QKV + (size_t)l * QKV_SZ),
            qkv_b + (size_t)l * TH, qkvP, nullptr, MM, TH, 3 * HH, 0);

        attn_tile_kernel<<<dim3(SS / 64, NHD, BB), 256, ATTN_SMEM>>>(qkvP, seq_mask, augN);

        gemm_mma_kernel<<<dim3(HH / 128, MM / 128), 256, GEMM_SMEM>>>(
            augN, waug + (size_t)3 * (OFF_RES + (size_t)l * RES_SZ),
            res_b + (size_t)l * HH, bP, nullptr, MM, HH, 3 * HH, 0);

        add_ln_kernel<<<MM, 256>>>(hP, bP, ln1_g + (size_t)l * HH, ln1_b + (size_t)l * HH, augN);

        gemm_mma_kernel<<<dim3(4 * HH / 128, MM / 128), 256, GEMM_SMEM>>>(
            augN, waug + (size_t)3 * (OFF_FF1 + (size_t)l * FF1_SZ),
            ff1_b + (size_t)l * 4 * HH, nullptr, augW, MM, 4 * HH, 3 * HH, 1);

        gemm_mma_kernel<<<dim3(HH / 128, MM / 128), 256, GEMM_SMEM>>>(
            augW, waug + (size_t)3 * (OFF_FF2 + (size_t)l * FF2_SZ),
            ff2_b + (size_t)l * HH, aP, nullptr, MM, HH, 3 * 4 * HH, 0);

        add_ln_kernel<<<MM, 256>>>(hP, aP, ln2_g + (size_t)l * HH, ln2_b + (size_t)l * HH, augN);
    }

    wt_conv_kernel<<<dim3(VV / 32, HH / 32), dim3(32, 8)>>>(
        pred_w, waug + (size_t)3 * OFF_PRED, HH, VV);
    gemm_mma_kernel<<<dim3(VV / 128, MM / 128), 256, GEMM_SMEM>>>(
        augN, waug + (size_t)3 * OFF_PRED, nullptr, out, nullptr, MM, VV, 3 * HH, 0);

    softmax_kernel<<<MM, 256>>>(out, out + (size_t)MM * VV);
}

// round 14
// speedup vs baseline: 2.7357x; 1.0778x over previous
#include <cuda_runtime.h>
#include <cuda_bf16.h>
#include <math.h>
#include <stdint.h>

#define BB 2
#define SS 1024
#define HH 768
#define NHD 12
#define HD 64
#define LL 4
#define VV 32000
#define MM (BB*SS)
#define TH (3*HH)

// ---------------- fp32 scratch -------------------------------------------------
__device__ float g_h[MM * HH];
__device__ float g_qkv[MM * TH];   // qkv result; reused as split-K partial planes later
__device__ float g_a[MM * HH];
__device__ float g_b[MM * HH];

// ---------------- augmented bf16 arenas ----------------------------------------
#define QKV_SZ (2304*768)
#define RES_SZ (768*768)
#define FF1_SZ (3072*768)
#define FF2_SZ (768*3072)
#define PRED_SZ (32000*768)
#define OFF_QKV 0
#define OFF_RES (4*QKV_SZ)
#define OFF_FF1 (OFF_RES + 4*RES_SZ)
#define OFF_FF2 (OFF_FF1 + 4*FF1_SZ)
#define OFF_PRED (OFF_FF2 + 4*FF2_SZ)
#define WT_TOTAL (OFF_PRED + PRED_SZ)

__device__ unsigned short g_waug[(size_t)3 * WT_TOTAL];
__device__ unsigned short g_augN[(size_t)MM * 3 * HH];
__device__ unsigned short g_augW[(size_t)MM * 3 * 4 * HH];

// ---------------- helpers -------------------------------------------------------
__device__ __forceinline__ uint32_t smem_u32(const void* p) {
    uint32_t a;
    asm("{ .reg .u64 t; cvta.to.shared.u64 t, %1; cvt.u32.u64 %0, t; }"
        : "=r"(a) : "l"(p));
    return a;
}
#define CP16(dst, src) \
    asm volatile("cp.async.cg.shared.global [%0], [%1], 16;" :: "r"(dst), "l"(src))
#define CP_COMMIT() asm volatile("cp.async.commit_group;" ::: "memory")
#define CP_WAIT1()  asm volatile("cp.async.wait_group 1;" ::: "memory")

__device__ __forceinline__ void ldm_x4(uint32_t* r, uint32_t addr) {
    asm volatile("ldmatrix.sync.aligned.m8n8.x4.shared.b16 {%0,%1,%2,%3}, [%4];"
                 : "=r"(r[0]), "=r"(r[1]), "=r"(r[2]), "=r"(r[3]) : "r"(addr));
}
__device__ __forceinline__ void mma16816(float* d, const uint32_t* a, const uint32_t* b) {
    asm volatile(
        "mma.sync.aligned.m16n8k16.row.col.f32.bf16.bf16.f32 "
        "{%0,%1,%2,%3}, {%4,%5,%6,%7}, {%8,%9}, {%0,%1,%2,%3};"
        : "+f"(d[0]), "+f"(d[1]), "+f"(d[2]), "+f"(d[3])
        : "r"(a[0]), "r"(a[1]), "r"(a[2]), "r"(a[3]), "r"(b[0]), "r"(b[1]));
}
__device__ __forceinline__ void split_bf16(float v, unsigned short& hi, unsigned short& lo) {
    __nv_bfloat16 h = __float2bfloat16_rn(v);
    hi = __bfloat16_as_ushort(h);
    lo = __bfloat16_as_ushort(__float2bfloat16_rn(v - __bfloat162float(h)));
}

// ---------------- weight conversion ---------------------------------------------
__global__ void wt_conv_kernel(const float* __restrict__ W,
                               unsigned short* __restrict__ Waug, int K, int N)
{
    __shared__ float t[32][33];
    int n0 = blockIdx.x * 32, k0 = blockIdx.y * 32;
    int tx = threadIdx.x, ty = threadIdx.y;
#pragma unroll
    for (int i = 0; i < 4; i++)
        t[ty + i * 8][tx] = W[(size_t)(k0 + ty + i * 8) * N + n0 + tx];
    __syncthreads();
    size_t K3 = (size_t)3 * K;
#pragma unroll
    for (int i = 0; i < 4; i++) {
        int n = n0 + ty + i * 8;
        int k = k0 + tx;
        float v = t[tx][ty + i * 8];
        unsigned short hu, lu;
        split_bf16(v, hu, lu);
        Waug[(size_t)n * K3 + k] = hu;
        Waug[(size_t)n * K3 + K + k] = hu;
        Waug[(size_t)n * K3 + 2 * K + k] = lu;
    }
}

// ---------------- bf16 HMMA GEMM (optional split-K via blockIdx.z) ---------------
#define BKP 40
#define STG_BYTES (2 * 128 * BKP * 2)
#define GEMM_SMEM (3 * STG_BYTES)

__global__ __launch_bounds__(256, 2)
void gemm_mma_kernel(const unsigned short* __restrict__ A,
                     const unsigned short* __restrict__ B,
                     const float* __restrict__ bias, float* __restrict__ C,
                     unsigned short* __restrict__ Caug,
                     float* __restrict__ Cpart,
                     int M, int N, int Ka, int gelu, int splitk)
{
    extern __shared__ char smem[];
    uint32_t sbase = smem_u32(smem);
    int tid = threadIdx.x;
    int wid = tid >> 5, lid = tid & 31;
    int row0 = blockIdx.y * 128, col0 = blockIdx.x * 128;
    int Kc = Ka / splitk;
    int koff = blockIdx.z * Kc;
    int KT = Kc >> 5;

    int lrow = tid & 127;
    int lhalf = tid >> 7;
    const char* gA = (const char*)(A + (size_t)(row0 + lrow) * Ka + koff) + lhalf * 32;
    const char* gB = (const char*)(B + (size_t)(col0 + lrow) * Ka + koff) + lhalf * 32;
    uint32_t sAw = sbase + lrow * 80 + lhalf * 32;
    uint32_t sBw = sbase + 128 * 80 + lrow * 80 + lhalf * 32;

#pragma unroll
    for (int s = 0; s < 2; s++) {
        const char* pa = gA + (size_t)s * 64;
        const char* pb = gB + (size_t)s * 64;
        uint32_t da = sAw + s * STG_BYTES;
        uint32_t db = sBw + s * STG_BYTES;
        CP16(da, pa); CP16(da + 16, pa + 16);
        CP16(db, pb); CP16(db + 16, pb + 16);
        CP_COMMIT();
    }

    int wm0 = (wid >> 2) * 64;
    int wn0 = (wid & 3) * 32;

    int a_r = ((lid >> 3) & 1) * 8 + (lid & 7);
    int a_k = ((lid >> 4) & 1) * 8;
    int b_r = ((lid >> 4) & 1) * 8 + (lid & 7);
    int b_k = ((lid >> 3) & 1) * 8;

    float acc[4][4][4];
#pragma unroll
    for (int i = 0; i < 4; i++)
#pragma unroll
        for (int j = 0; j < 4; j++)
#pragma unroll
            for (int q = 0; q < 4; q++) acc[i][j][q] = 0.f;

    for (int kt = 0; kt < KT; kt++) {
        CP_WAIT1();
        __syncthreads();
        if (kt + 2 < KT) {
            int s = (kt + 2) % 3;
            const char* pa = gA + (size_t)(kt + 2) * 64;
            const char* pb = gB + (size_t)(kt + 2) * 64;
            uint32_t da = sAw + s * STG_BYTES;
            uint32_t db = sBw + s * STG_BYTES;
            CP16(da, pa); CP16(da + 16, pa + 16);
            CP16(db, pb); CP16(db + 16, pb + 16);
        }
        CP_COMMIT();

        uint32_t stA = sbase + (kt % 3) * STG_BYTES;
        uint32_t stB = stA + 128 * 80;
#pragma unroll
        for (int ks = 0; ks < 2; ks++) {
            uint32_t a[4][4];
#pragma unroll
            for (int mi = 0; mi < 4; mi++) {
                uint32_t addr = stA + (wm0 + mi * 16 + a_r) * 80 + (ks * 16 + a_k) * 2;
                ldm_x4(a[mi], addr);
            }
            uint32_t b[2][4];
#pragma unroll
            for (int pi = 0; pi < 2; pi++) {
                uint32_t addr = stB + (wn0 + pi * 16 + b_r) * 80 + (ks * 16 + b_k) * 2;
                ldm_x4(b[pi], addr);
            }
#pragma unroll
            for (int mi = 0; mi < 4; mi++) {
#pragma unroll
                for (int ni = 0; ni < 4; ni++) {
                    mma16816(acc[mi][ni], a[mi], &b[ni >> 1][(ni & 1) * 2]);
                }
            }
        }
    }

    int qr = lid >> 2;
    int qc = (lid & 3) * 2;
    size_t N3 = (size_t)3 * N;

    if (splitk > 1) {
        float* plane = Cpart + (size_t)blockIdx.z * M * N;
#pragma unroll
        for (int mi = 0; mi < 4; mi++) {
#pragma unroll
            for (int ni = 0; ni < 4; ni++) {
                int col = col0 + wn0 + ni * 8 + qc;
#pragma unroll
                for (int h = 0; h < 2; h++) {
                    int row = row0 + wm0 + mi * 16 + qr + h * 8;
                    float2 o;
                    o.x = acc[mi][ni][h * 2 + 0];
                    o.y = acc[mi][ni][h * 2 + 1];
                    *(float2*)(plane + (size_t)row * N + col) = o;
                }
            }
        }
        return;
    }

#pragma unroll
    for (int mi = 0; mi < 4; mi++) {
#pragma unroll
        for (int ni = 0; ni < 4; ni++) {
            int col = col0 + wn0 + ni * 8 + qc;
            float b0 = 0.f, b1 = 0.f;
            if (bias) { b0 = bias[col]; b1 = bias[col + 1]; }
#pragma unroll
            for (int h = 0; h < 2; h++) {
                int row = row0 + wm0 + mi * 16 + qr + h * 8;
                float v0 = acc[mi][ni][h * 2 + 0] + b0;
                float v1 = acc[mi][ni][h * 2 + 1] + b1;
                if (gelu) {
                    v0 = 0.5f * v0 * (1.f + erff(v0 * 0.70710678118654752f));
                    v1 = 0.5f * v1 * (1.f + erff(v1 * 0.70710678118654752f));
                }
                if (C) {
                    float2 o; o.x = v0; o.y = v1;
                    *(float2*)(C + (size_t)row * N + col) = o;
                }
                if (Caug) {
                    unsigned short h0, l0, h1, l1;
                    split_bf16(v0, h0, l0);
                    split_bf16(v1, h1, l1);
                    unsigned short* base = Caug + (size_t)row * N3 + col;
                    ushort2 hv; hv.x = h0; hv.y = h1;
                    ushort2 lv; lv.x = l0; lv.y = l1;
                    *(ushort2*)(base) = hv;
                    *(ushort2*)(base + N) = lv;
                    *(ushort2*)(base + 2 * N) = hv;
                }
            }
        }
    }
}

// ---------------- split-K reduce: C = p0 + p1 + p2 + bias ------------------------
__global__ void reduce3_bias_kernel(const float* __restrict__ p,
                                    const float* __restrict__ bias,
                                    float* __restrict__ C, int N)
{
    int row = blockIdx.x;
    size_t plane = (size_t)MM * N;
    const float* p0 = p + (size_t)row * N;
    const float* p1 = p0 + plane;
    const float* p2 = p1 + plane;
    float* crow = C + (size_t)row * N;
    for (int i = threadIdx.x; i < N; i += blockDim.x)
        crow[i] = p0[i] + p1[i] + p2[i] + bias[i];
}

// ---------------- embedding (writes h fp32 + narrow aug) ------------------------
__global__ void embed_kernel(const int* __restrict__ ids,
                             const float* __restrict__ bpe,
                             const float* __restrict__ pos,
                             float* __restrict__ h,
                             unsigned short* __restrict__ aug)
{
    int row = blockIdx.x;
    int s = row % SS;
    int id = ids[row];
    const float* brow = bpe + (size_t)id * HH;
    const float* prow = pos + (size_t)s * HH;
    float* hrow = h + (size_t)row * HH;
    unsigned short* arow = aug + (size_t)row * 3 * HH;
    for (int i = threadIdx.x; i < HH; i += blockDim.x) {
        float v = brow[i] + prow[i];
        hrow[i] = v;
        unsigned short hu, lu;
        split_bf16(v, hu, lu);
        arow[i] = hu;
        arow[HH + i] = lu;
        arow[2 * HH + i] = hu;
    }
}

// ---------------- tiled flash-style attention (writes narrow aug directly) ------
#define ATTN_SMEM ((4 * 4096 + 64) * 4)

__global__ __launch_bounds__(256, 2)
void attn_tile_kernel(const float* __restrict__ qkv,
                      const float* __restrict__ seq_mask,
                      unsigned short* __restrict__ outaug)
{
    extern __shared__ float smf[];
    float* Qt = smf;
    float* Kt = smf + 4096;
    float* Vs = smf + 8192;
    float* Pt = smf + 12288;
    float* msk = smf + 16384;

    int qt = blockIdx.x, h = blockIdx.y, b = blockIdx.z;
    int tid = threadIdx.x;
    int qg = tid >> 4;
    int lg = tid & 15;
    int q0 = qg * 4;
    int j0 = lg * 4;
    int tok_q0 = qt * 64;

#pragma unroll
    for (int i = 0; i < 4; i++) {
        int idx = tid + i * 256;
        int tk = idx >> 4;
        int d4 = (idx & 15) * 4;
        const float4 v = *(const float4*)(qkv + (size_t)(b * SS + tok_q0 + tk) * TH + h * HD + d4);
        Qt[(d4 + 0) * 64 + tk] = v.x;
        Qt[(d4 + 1) * 64 + tk] = v.y;
        Qt[(d4 + 2) * 64 + tk] = v.z;
        Qt[(d4 + 3) * 64 + tk] = v.w;
    }

    float O[4][4];
    float M[4], L[4];
#pragma unroll
    for (int qi = 0; qi < 4; qi++) {
        M[qi] = -1e30f; L[qi] = 0.f;
#pragma unroll
        for (int di = 0; di < 4; di++) O[qi][di] = 0.f;
    }

    for (int kt = 0; kt <= qt; kt++) {
        int tok_k0 = kt * 64;
        __syncthreads();
#pragma unroll
        for (int i = 0; i < 4; i++) {
            int idx = tid + i * 256;
            int tk = idx >> 4;
            int d4 = (idx & 15) * 4;
            const float* rowp = qkv + (size_t)(b * SS + tok_k0 + tk) * TH + h * HD;
            float4 kv = *(const float4*)(rowp + HH + d4);
            Kt[(d4 + 0) * 64 + tk] = kv.x;
            Kt[(d4 + 1) * 64 + tk] = kv.y;
            Kt[(d4 + 2) * 64 + tk] = kv.z;
            Kt[(d4 + 3) * 64 + tk] = kv.w;
            float4 vv = *(const float4*)(rowp + 2 * HH + d4);
            *(float4*)(Vs + tk * 64 + d4) = vv;
        }
        if (tid < 64) msk[tid] = seq_mask[b * SS + tok_k0 + tid];
        __syncthreads();

        float s[4][4];
#pragma unroll
        for (int qi = 0; qi < 4; qi++)
#pragma unroll
            for (int ji = 0; ji < 4; ji++) s[qi][ji] = 0.f;
        for (int d = 0; d < 64; d++) {
            const float4 qv = *(const float4*)(Qt + d * 64 + q0);
            const float4 kv = *(const float4*)(Kt + d * 64 + j0);
            float qa[4] = {qv.x, qv.y, qv.z, qv.w};
            float ka[4] = {kv.x, kv.y, kv.z, kv.w};
#pragma unroll
            for (int qi = 0; qi < 4; qi++)
#pragma unroll
                for (int ji = 0; ji < 4; ji++)
                    s[qi][ji] = fmaf(qa[qi], ka[ji], s[qi][ji]);
        }
#pragma unroll
        for (int qi = 0; qi < 4; qi++) {
            int gq = tok_q0 + q0 + qi;
#pragma unroll
            for (int ji = 0; ji < 4; ji++) {
                int gj = tok_k0 + j0 + ji;
                float v = s[qi][ji] * 0.125f + (1.0f - msk[j0 + ji]) * -1e9f;
                s[qi][ji] = (gj <= gq) ? v : -1e30f;
            }
        }
#pragma unroll
        for (int qi = 0; qi < 4; qi++) {
            float mt = fmaxf(fmaxf(s[qi][0], s[qi][1]), fmaxf(s[qi][2], s[qi][3]));
#pragma unroll
            for (int o = 1; o < 16; o <<= 1)
                mt = fmaxf(mt, __shfl_xor_sync(0xffffffffu, mt, o, 16));
            float Mn = fmaxf(M[qi], mt);
            float sc = expf(M[qi] - Mn);
            float ps = 0.f;
#pragma unroll
            for (int ji = 0; ji < 4; ji++) {
                float pv = expf(s[qi][ji] - Mn);
                s[qi][ji] = pv;
                ps += pv;
            }
            L[qi] = L[qi] * sc + ps;
#pragma unroll
            for (int di = 0; di < 4; di++) O[qi][di] *= sc;
            M[qi] = Mn;
        }
#pragma unroll
        for (int qi = 0; qi < 4; qi++)
#pragma unroll
            for (int ji = 0; ji < 4; ji++)
                Pt[(j0 + ji) * 64 + q0 + qi] = s[qi][ji];
        __syncthreads();

        int d0 = lg * 4;
        for (int j = 0; j < 64; j++) {
            const float4 pv = *(const float4*)(Pt + j * 64 + q0);
            const float4 vv = *(const float4*)(Vs + j * 64 + d0);
            float pa[4] = {pv.x, pv.y, pv.z, pv.w};
            float va[4] = {vv.x, vv.y, vv.z, vv.w};
#pragma unroll
            for (int qi = 0; qi < 4; qi++)
#pragma unroll
                for (int di = 0; di < 4; di++)
                    O[qi][di] = fmaf(pa[qi], va[di], O[qi][di]);
        }
    }

#pragma unroll
    for (int qi = 0; qi < 4; qi++) {
        float l = L[qi];
#pragma unroll
        for (int o = 1; o < 16; o <<= 1)
            l += __shfl_xor_sync(0xffffffffu, l, o, 16);
        float inv = 1.0f / l;
        int col = h * HD + lg * 4;
        unsigned short* base = outaug + (size_t)(b * SS + tok_q0 + q0 + qi) * 3 * HH + col;
        ushort4 hv, lv;
        unsigned short hu, lu;
        split_bf16(O[qi][0] * inv, hu, lu); hv.x = hu; lv.x = lu;
        split_bf16(O[qi][1] * inv, hu, lu); hv.y = hu; lv.y = lu;
        split_bf16(O[qi][2] * inv, hu, lu); hv.z = hu; lv.z = lu;
        split_bf16(O[qi][3] * inv, hu, lu); hv.w = hu; lv.w = lu;
        *(ushort4*)(base) = hv;
        *(ushort4*)(base + HH) = lv;
        *(ushort4*)(base + 2 * HH) = hv;
    }
}

// ---------------- add + layernorm (writes h fp32 + narrow aug) -------------------
__global__ void add_ln_kernel(float* __restrict__ h, const float* __restrict__ a,
                              const float* __restrict__ g, const float* __restrict__ bt,
                              unsigned short* __restrict__ aug)
{
    int row = blockIdx.x;
    int tid = threadIdx.x;
    __shared__ float buf[HH];
    __shared__ float red[256];

    float* hrow = h + (size_t)row * HH;
    const float* arow = a + (size_t)row * HH;
    unsigned short* grow = aug + (size_t)row * 3 * HH;

    float lsum = 0.f;
#pragma unroll
    for (int i = 0; i < 3; i++) {
        int idx = tid + i * 256;
        float v = hrow[idx] + arow[idx];
        buf[idx] = v;
        lsum += v;
    }
    red[tid] = lsum;
    __syncthreads();
    for (int off = 128; off > 0; off >>= 1) {
        if (tid < off) red[tid] += red[tid + off];
        __syncthreads();
    }
    float mean = red[0] * (1.0f / HH);
    __syncthreads();

    float lvar = 0.f;
#pragma unroll
    for (int i = 0; i < 3; i++) {
        int idx = tid + i * 256;
        float d = buf[idx] - mean;
        lvar += d * d;
    }
    red[tid] = lvar;
    __syncthreads();
    for (int off = 128; off > 0; off >>= 1) {
        if (tid < off) red[tid] += red[tid + off];
        __syncthreads();
    }
    float rstd = rsqrtf(red[0] * (1.0f / HH) + 1e-5f);

#pragma unroll
    for (int i = 0; i < 3; i++) {
        int idx = tid + i * 256;
        float y = g[idx] * ((buf[idx] - mean) * rstd) + bt[idx];
        hrow[idx] = y;
        unsigned short hu, lu;
        split_bf16(y, hu, lu);
        grow[idx] = hu;
        grow[HH + idx] = lu;
        grow[2 * HH + idx] = hu;
    }
}

// ---------------- vocab softmax (online) -----------------------------------------
__global__ void softmax_kernel(const float* __restrict__ x, float* __restrict__ p)
{
    int row = blockIdx.x;
    int tid = threadIdx.x;
    __shared__ float rm[256], rl[256];
    const float* xr = x + (size_t)row * VV;
    float* pr = p + (size_t)row * VV;

    float m = -3.0e38f, l = 0.f;
    for (int i = tid; i < VV; i += 256) {
        float v = xr[i];
        if (v > m) { l = l * expf(m - v) + 1.0f; m = v; }
        else l += expf(v - m);
    }
    rm[tid] = m; rl[tid] = l;
    __syncthreads();
    for (int off = 128; off > 0; off >>= 1) {
        if (tid < off) {
            float m2 = rm[tid + off], l2 = rl[tid + off];
            float Mx = fmaxf(rm[tid], m2);
            rl[tid] = rl[tid] * expf(rm[tid] - Mx) + l2 * expf(m2 - Mx);
            rm[tid] = Mx;
        }
        __syncthreads();
    }
    float Mx = rm[0];
    float inv = 1.0f / rl[0];

    for (int i = tid; i < VV; i += 256) pr[i] = expf(xr[i] - Mx) * inv;
}

// ---------------- launch --------------------------------------------------------
extern "C" void kernel_launch(void* const* d_in, const int* in_sizes, int n_in,
                              void* d_out, int out_size)
{
    const int*   ids      = (const int*)d_in[0];
    const float* seq_mask = (const float*)d_in[1];
    const float* bpe      = (const float*)d_in[2];
    const float* pos      = (const float*)d_in[3];
    const float* qkv_w    = (const float*)d_in[4];
    const float* qkv_b    = (const float*)d_in[5];
    const float* res_w    = (const float*)d_in[6];
    const float* res_b    = (const float*)d_in[7];
    const float* ln1_g    = (const float*)d_in[8];
    const float* ln1_b    = (const float*)d_in[9];
    const float* ff1_w    = (const float*)d_in[10];
    const float* ff1_b    = (const float*)d_in[11];
    const float* ff2_w    = (const float*)d_in[12];
    const float* ff2_b    = (const float*)d_in[13];
    const float* ln2_g    = (const float*)d_in[14];
    const float* ln2_b    = (const float*)d_in[15];
    const float* pred_w   = (const float*)d_in[16];
    float* out = (float*)d_out;

    float *hP, *qkvP, *aP, *bP;
    unsigned short *waug, *augN, *augW;
    cudaGetSymbolAddress((void**)&hP, g_h);
    cudaGetSymbolAddress((void**)&qkvP, g_qkv);
    cudaGetSymbolAddress((void**)&aP, g_a);
    cudaGetSymbolAddress((void**)&bP, g_b);
    cudaGetSymbolAddress((void**)&waug, g_waug);
    cudaGetSymbolAddress((void**)&augN, g_augN);
    cudaGetSymbolAddress((void**)&augW, g_augW);

    cudaFuncSetAttribute(gemm_mma_kernel, cudaFuncAttributeMaxDynamicSharedMemorySize,
                         GEMM_SMEM);
    cudaFuncSetAttribute(attn_tile_kernel, cudaFuncAttributeMaxDynamicSharedMemorySize,
                         ATTN_SMEM);

    embed_kernel<<<MM, 256>>>(ids, bpe, pos, hP, augN);

    for (int l = 0; l < LL; l++) {
        wt_conv_kernel<<<dim3(TH / 32, HH / 32), dim3(32, 8)>>>(
            qkv_w + (size_t)l * QKV_SZ, waug + (size_t)3 * (OFF_QKV + (size_t)l * QKV_SZ), HH, TH);
        wt_conv_kernel<<<dim3(HH / 32, HH / 32), dim3(32, 8)>>>(
            res_w + (size_t)l * RES_SZ, waug + (size_t)3 * (OFF_RES + (size_t)l * RES_SZ), HH, HH);
        wt_conv_kernel<<<dim3(4 * HH / 32, HH / 32), dim3(32, 8)>>>(
            ff1_w + (size_t)l * FF1_SZ, waug + (size_t)3 * (OFF_FF1 + (size_t)l * FF1_SZ), HH, 4 * HH);
        wt_conv_kernel<<<dim3(HH / 32, 4 * HH / 32), dim3(32, 8)>>>(
            ff2_w + (size_t)l * FF2_SZ, waug + (size_t)3 * (OFF_FF2 + (size_t)l * FF2_SZ), 4 * HH, HH);

        gemm_mma_kernel<<<dim3(TH / 128, MM / 128), 256, GEMM_SMEM>>>(
            augN, waug + (size_t)3 * (OFF_QKV + (size_t)l * QKV_SZ),
            qkv_b + (size_t)l * TH, qkvP, nullptr, nullptr, MM, TH, 3 * HH, 0, 1);

        attn_tile_kernel<<<dim3(SS / 64, NHD, BB), 256, ATTN_SMEM>>>(qkvP, seq_mask, augN);

        gemm_mma_kernel<<<dim3(HH / 128, MM / 128, 3), 256, GEMM_SMEM>>>(
            augN, waug + (size_t)3 * (OFF_RES + (size_t)l * RES_SZ),
            nullptr, nullptr, nullptr, qkvP, MM, HH, 3 * HH, 0, 3);
        reduce3_bias_kernel<<<MM, 256>>>(qkvP, res_b + (size_t)l * HH, bP, HH);

        add_ln_kernel<<<MM, 256>>>(hP, bP, ln1_g + (size_t)l * HH, ln1_b + (size_t)l * HH, augN);

        gemm_mma_kernel<<<dim3(4 * HH / 128, MM / 128), 256, GEMM_SMEM>>>(
            augN, waug + (size_t)3 * (OFF_FF1 + (size_t)l * FF1_SZ),
            ff1_b + (size_t)l * 4 * HH, nullptr, augW, nullptr, MM, 4 * HH, 3 * HH, 1, 1);

        gemm_mma_kernel<<<dim3(HH / 128, MM / 128, 3), 256, GEMM_SMEM>>>(
            augW, waug + (size_t)3 * (OFF_FF2 + (size_t)l * FF2_SZ),
            nullptr, nullptr, nullptr, qkvP, MM, HH, 3 * 4 * HH, 0, 3);
        reduce3_bias_kernel<<<MM, 256>>>(qkvP, ff2_b + (size_t)l * HH, aP, HH);

        add_ln_kernel<<<MM, 256>>>(hP, aP, ln2_g + (size_t)l * HH, ln2_b + (size_t)l * HH, augN);
    }

    wt_conv_kernel<<<dim3(VV / 32, HH / 32), dim3(32, 8)>>>(
        pred_w, waug + (size_t)3 * OFF_PRED, HH, VV);
    gemm_mma_kernel<<<dim3(VV / 128, MM / 128), 256, GEMM_SMEM>>>(
        augN, waug + (size_t)3 * OFF_PRED, nullptr, out, nullptr, nullptr, MM, VV, 3 * HH, 0, 1);

    softmax_kernel<<<MM, 256>>>(out, out + (size_t)MM * VV);
}

// round 15
// speedup vs baseline: 2.9326x; 1.0720x over previous
#include <cuda_runtime.h>
#include <cuda_bf16.h>
#include <math.h>
#include <stdint.h>

#define BB 2
#define SS 1024
#define HH 768
#define NHD 12
#define HD 64
#define LL 4
#define VV 32000
#define MM (BB*SS)
#define TH (3*HH)

// ---------------- fp32 scratch -------------------------------------------------
__device__ float g_h[MM * HH];
__device__ float g_qkv[MM * TH];   // qkv result; reused as split-K partial planes
__device__ float g_a[MM * HH];
__device__ float g_b[MM * HH];

// ---------------- augmented bf16 arenas ----------------------------------------
#define QKV_SZ (2304*768)
#define RES_SZ (768*768)
#define FF1_SZ (3072*768)
#define FF2_SZ (768*3072)
#define PRED_SZ (32000*768)
#define OFF_QKV 0
#define OFF_RES (4*QKV_SZ)
#define OFF_FF1 (OFF_RES + 4*RES_SZ)
#define OFF_FF2 (OFF_FF1 + 4*FF1_SZ)
#define OFF_PRED (OFF_FF2 + 4*FF2_SZ)
#define WT_TOTAL (OFF_PRED + PRED_SZ)

__device__ unsigned short g_waug[(size_t)3 * WT_TOTAL];
__device__ unsigned short g_augN[(size_t)MM * 3 * HH];
__device__ unsigned short g_augW[(size_t)MM * 3 * 4 * HH];

// ---------------- helpers -------------------------------------------------------
__device__ __forceinline__ uint32_t smem_u32(const void* p) {
    uint32_t a;
    asm("{ .reg .u64 t; cvta.to.shared.u64 t, %1; cvt.u32.u64 %0, t; }"
        : "=r"(a) : "l"(p));
    return a;
}
#define CP16(dst, src) \
    asm volatile("cp.async.cg.shared.global [%0], [%1], 16;" :: "r"(dst), "l"(src))
#define CP_COMMIT() asm volatile("cp.async.commit_group;" ::: "memory")
#define CP_WAIT1()  asm volatile("cp.async.wait_group 1;" ::: "memory")

__device__ __forceinline__ void ldm_x4(uint32_t* r, uint32_t addr) {
    asm volatile("ldmatrix.sync.aligned.m8n8.x4.shared.b16 {%0,%1,%2,%3}, [%4];"
                 : "=r"(r[0]), "=r"(r[1]), "=r"(r[2]), "=r"(r[3]) : "r"(addr));
}
__device__ __forceinline__ void mma16816(float* d, const uint32_t* a, const uint32_t* b) {
    asm volatile(
        "mma.sync.aligned.m16n8k16.row.col.f32.bf16.bf16.f32 "
        "{%0,%1,%2,%3}, {%4,%5,%6,%7}, {%8,%9}, {%0,%1,%2,%3};"
        : "+f"(d[0]), "+f"(d[1]), "+f"(d[2]), "+f"(d[3])
        : "r"(a[0]), "r"(a[1]), "r"(a[2]), "r"(a[3]), "r"(b[0]), "r"(b[1]));
}
__device__ __forceinline__ void split_bf16(float v, unsigned short& hi, unsigned short& lo) {
    __nv_bfloat16 h = __float2bfloat16_rn(v);
    hi = __bfloat16_as_ushort(h);
    lo = __bfloat16_as_ushort(__float2bfloat16_rn(v - __bfloat162float(h)));
}

// ---------------- weight conversion ---------------------------------------------
__global__ void wt_conv_kernel(const float* __restrict__ W,
                               unsigned short* __restrict__ Waug, int K, int N)
{
    __shared__ float t[32][33];
    int n0 = blockIdx.x * 32, k0 = blockIdx.y * 32;
    int tx = threadIdx.x, ty = threadIdx.y;
#pragma unroll
    for (int i = 0; i < 4; i++)
        t[ty + i * 8][tx] = W[(size_t)(k0 + ty + i * 8) * N + n0 + tx];
    __syncthreads();
    size_t K3 = (size_t)3 * K;
#pragma unroll
    for (int i = 0; i < 4; i++) {
        int n = n0 + ty + i * 8;
        int k = k0 + tx;
        float v = t[tx][ty + i * 8];
        unsigned short hu, lu;
        split_bf16(v, hu, lu);
        Waug[(size_t)n * K3 + k] = hu;
        Waug[(size_t)n * K3 + K + k] = hu;
        Waug[(size_t)n * K3 + 2 * K + k] = lu;
    }
}

// ---------------- bf16 HMMA GEMM, BK=64, 3-stage, optional split-K --------------
#define ROWB 144                           // padded row stride in bytes (64 bf16 + 8 pad)
#define STG_BYTES (2 * 128 * ROWB)         // A + B tile per stage = 36864
#define GEMM_SMEM (3 * STG_BYTES)          // 110592

__global__ __launch_bounds__(256, 2)
void gemm_mma_kernel(const unsigned short* __restrict__ A,
                     const unsigned short* __restrict__ B,
                     const float* __restrict__ bias, float* __restrict__ C,
                     unsigned short* __restrict__ Caug,
                     float* __restrict__ Cpart,
                     int M, int N, int Ka, int gelu, int splitk)
{
    extern __shared__ char smem[];
    uint32_t sbase = smem_u32(smem);
    int tid = threadIdx.x;
    int wid = tid >> 5, lid = tid & 31;
    int row0 = blockIdx.y * 128, col0 = blockIdx.x * 128;
    int Kc = Ka / splitk;
    int koff = blockIdx.z * Kc;
    int KT = Kc >> 6;

    // loader: thread t owns row t>>1, 64-byte half t&1
    int lrow = tid >> 1;
    int lhalf = tid & 1;
    const char* gA = (const char*)(A + (size_t)(row0 + lrow) * Ka + koff) + lhalf * 64;
    const char* gB = (const char*)(B + (size_t)(col0 + lrow) * Ka + koff) + lhalf * 64;
    uint32_t sAw = sbase + lrow * ROWB + lhalf * 64;
    uint32_t sBw = sbase + 128 * ROWB + lrow * ROWB + lhalf * 64;

#pragma unroll
    for (int s = 0; s < 2; s++) {
        const char* pa = gA + (size_t)s * 128;
        const char* pb = gB + (size_t)s * 128;
        uint32_t da = sAw + s * STG_BYTES;
        uint32_t db = sBw + s * STG_BYTES;
        CP16(da, pa); CP16(da + 16, pa + 16); CP16(da + 32, pa + 32); CP16(da + 48, pa + 48);
        CP16(db, pb); CP16(db + 16, pb + 16); CP16(db + 32, pb + 32); CP16(db + 48, pb + 48);
        CP_COMMIT();
    }

    int wm0 = (wid >> 2) * 64;
    int wn0 = (wid & 3) * 32;

    int a_r = ((lid >> 3) & 1) * 8 + (lid & 7);
    int a_k = ((lid >> 4) & 1) * 8;
    int b_r = ((lid >> 4) & 1) * 8 + (lid & 7);
    int b_k = ((lid >> 3) & 1) * 8;

    float acc[4][4][4];
#pragma unroll
    for (int i = 0; i < 4; i++)
#pragma unroll
        for (int j = 0; j < 4; j++)
#pragma unroll
            for (int q = 0; q < 4; q++) acc[i][j][q] = 0.f;

    for (int kt = 0; kt < KT; kt++) {
        CP_WAIT1();
        __syncthreads();
        if (kt + 2 < KT) {
            int s = (kt + 2) % 3;
            const char* pa = gA + (size_t)(kt + 2) * 128;
            const char* pb = gB + (size_t)(kt + 2) * 128;
            uint32_t da = sAw + s * STG_BYTES;
            uint32_t db = sBw + s * STG_BYTES;
            CP16(da, pa); CP16(da + 16, pa + 16); CP16(da + 32, pa + 32); CP16(da + 48, pa + 48);
            CP16(db, pb); CP16(db + 16, pb + 16); CP16(db + 32, pb + 32); CP16(db + 48, pb + 48);
        }
        CP_COMMIT();

        uint32_t stA = sbase + (kt % 3) * STG_BYTES;
        uint32_t stB = stA + 128 * ROWB;
#pragma unroll
        for (int ks = 0; ks < 4; ks++) {
            uint32_t a[4][4];
#pragma unroll
            for (int mi = 0; mi < 4; mi++) {
                uint32_t addr = stA + (wm0 + mi * 16 + a_r) * ROWB + (ks * 16 + a_k) * 2;
                ldm_x4(a[mi], addr);
            }
            uint32_t b[2][4];
#pragma unroll
            for (int pi = 0; pi < 2; pi++) {
                uint32_t addr = stB + (wn0 + pi * 16 + b_r) * ROWB + (ks * 16 + b_k) * 2;
                ldm_x4(b[pi], addr);
            }
#pragma unroll
            for (int mi = 0; mi < 4; mi++) {
#pragma unroll
                for (int ni = 0; ni < 4; ni++) {
                    mma16816(acc[mi][ni], a[mi], &b[ni >> 1][(ni & 1) * 2]);
                }
            }
        }
    }

    int qr = lid >> 2;
    int qc = (lid & 3) * 2;
    size_t N3 = (size_t)3 * N;

    if (splitk > 1) {
        float* plane = Cpart + (size_t)blockIdx.z * M * N;
#pragma unroll
        for (int mi = 0; mi < 4; mi++) {
#pragma unroll
            for (int ni = 0; ni < 4; ni++) {
                int col = col0 + wn0 + ni * 8 + qc;
#pragma unroll
                for (int h = 0; h < 2; h++) {
                    int row = row0 + wm0 + mi * 16 + qr + h * 8;
                    float2 o;
                    o.x = acc[mi][ni][h * 2 + 0];
                    o.y = acc[mi][ni][h * 2 + 1];
                    *(float2*)(plane + (size_t)row * N + col) = o;
                }
            }
        }
        return;
    }

#pragma unroll
    for (int mi = 0; mi < 4; mi++) {
#pragma unroll
        for (int ni = 0; ni < 4; ni++) {
            int col = col0 + wn0 + ni * 8 + qc;
            float b0 = 0.f, b1 = 0.f;
            if (bias) { b0 = bias[col]; b1 = bias[col + 1]; }
#pragma unroll
            for (int h = 0; h < 2; h++) {
                int row = row0 + wm0 + mi * 16 + qr + h * 8;
                float v0 = acc[mi][ni][h * 2 + 0] + b0;
                float v1 = acc[mi][ni][h * 2 + 1] + b1;
                if (gelu) {
                    v0 = 0.5f * v0 * (1.f + erff(v0 * 0.70710678118654752f));
                    v1 = 0.5f * v1 * (1.f + erff(v1 * 0.70710678118654752f));
                }
                if (C) {
                    float2 o; o.x = v0; o.y = v1;
                    *(float2*)(C + (size_t)row * N + col) = o;
                }
                if (Caug) {
                    unsigned short h0, l0, h1, l1;
                    split_bf16(v0, h0, l0);
                    split_bf16(v1, h1, l1);
                    unsigned short* base = Caug + (size_t)row * N3 + col;
                    ushort2 hv; hv.x = h0; hv.y = h1;
                    ushort2 lv; lv.x = l0; lv.y = l1;
                    *(ushort2*)(base) = hv;
                    *(ushort2*)(base + N) = lv;
                    *(ushort2*)(base + 2 * N) = hv;
                }
            }
        }
    }
}

// ---------------- split-K reduce: C = p0 + p1 + p2 + bias ------------------------
__global__ void reduce3_bias_kernel(const float* __restrict__ p,
                                    const float* __restrict__ bias,
                                    float* __restrict__ C, int N)
{
    int row = blockIdx.x;
    size_t plane = (size_t)MM * N;
    const float* p0 = p + (size_t)row * N;
    const float* p1 = p0 + plane;
    const float* p2 = p1 + plane;
    float* crow = C + (size_t)row * N;
    for (int i = threadIdx.x; i < N; i += blockDim.x)
        crow[i] = p0[i] + p1[i] + p2[i] + bias[i];
}

// ---------------- embedding (writes h fp32 + narrow aug) ------------------------
__global__ void embed_kernel(const int* __restrict__ ids,
                             const float* __restrict__ bpe,
                             const float* __restrict__ pos,
                             float* __restrict__ h,
                             unsigned short* __restrict__ aug)
{
    int row = blockIdx.x;
    int s = row % SS;
    int id = ids[row];
    const float* brow = bpe + (size_t)id * HH;
    const float* prow = pos + (size_t)s * HH;
    float* hrow = h + (size_t)row * HH;
    unsigned short* arow = aug + (size_t)row * 3 * HH;
    for (int i = threadIdx.x; i < HH; i += blockDim.x) {
        float v = brow[i] + prow[i];
        hrow[i] = v;
        unsigned short hu, lu;
        split_bf16(v, hu, lu);
        arow[i] = hu;
        arow[HH + i] = lu;
        arow[2 * HH + i] = hu;
    }
}

// ---------------- tiled flash-style attention (writes narrow aug directly) ------
#define ATTN_SMEM ((4 * 4096 + 64) * 4)

__global__ __launch_bounds__(256, 2)
void attn_tile_kernel(const float* __restrict__ qkv,
                      const float* __restrict__ seq_mask,
                      unsigned short* __restrict__ outaug)
{
    extern __shared__ float smf[];
    float* Qt = smf;
    float* Kt = smf + 4096;
    float* Vs = smf + 8192;
    float* Pt = smf + 12288;
    float* msk = smf + 16384;

    int qt = blockIdx.x, h = blockIdx.y, b = blockIdx.z;
    int tid = threadIdx.x;
    int qg = tid >> 4;
    int lg = tid & 15;
    int q0 = qg * 4;
    int j0 = lg * 4;
    int tok_q0 = qt * 64;

#pragma unroll
    for (int i = 0; i < 4; i++) {
        int idx = tid + i * 256;
        int tk = idx >> 4;
        int d4 = (idx & 15) * 4;
        const float4 v = *(const float4*)(qkv + (size_t)(b * SS + tok_q0 + tk) * TH + h * HD + d4);
        Qt[(d4 + 0) * 64 + tk] = v.x;
        Qt[(d4 + 1) * 64 + tk] = v.y;
        Qt[(d4 + 2) * 64 + tk] = v.z;
        Qt[(d4 + 3) * 64 + tk] = v.w;
    }

    float O[4][4];
    float M[4], L[4];
#pragma unroll
    for (int qi = 0; qi < 4; qi++) {
        M[qi] = -1e30f; L[qi] = 0.f;
#pragma unroll
        for (int di = 0; di < 4; di++) O[qi][di] = 0.f;
    }

    for (int kt = 0; kt <= qt; kt++) {
        int tok_k0 = kt * 64;
        __syncthreads();
#pragma unroll
        for (int i = 0; i < 4; i++) {
            int idx = tid + i * 256;
            int tk = idx >> 4;
            int d4 = (idx & 15) * 4;
            const float* rowp = qkv + (size_t)(b * SS + tok_k0 + tk) * TH + h * HD;
            float4 kv = *(const float4*)(rowp + HH + d4);
            Kt[(d4 + 0) * 64 + tk] = kv.x;
            Kt[(d4 + 1) * 64 + tk] = kv.y;
            Kt[(d4 + 2) * 64 + tk] = kv.z;
            Kt[(d4 + 3) * 64 + tk] = kv.w;
            float4 vv = *(const float4*)(rowp + 2 * HH + d4);
            *(float4*)(Vs + tk * 64 + d4) = vv;
        }
        if (tid < 64) msk[tid] = seq_mask[b * SS + tok_k0 + tid];
        __syncthreads();

        float s[4][4];
#pragma unroll
        for (int qi = 0; qi < 4; qi++)
#pragma unroll
            for (int ji = 0; ji < 4; ji++) s[qi][ji] = 0.f;
        for (int d = 0; d < 64; d++) {
            const float4 qv = *(const float4*)(Qt + d * 64 + q0);
            const float4 kv = *(const float4*)(Kt + d * 64 + j0);
            float qa[4] = {qv.x, qv.y, qv.z, qv.w};
            float ka[4] = {kv.x, kv.y, kv.z, kv.w};
#pragma unroll
            for (int qi = 0; qi < 4; qi++)
#pragma unroll
                for (int ji = 0; ji < 4; ji++)
                    s[qi][ji] = fmaf(qa[qi], ka[ji], s[qi][ji]);
        }
#pragma unroll
        for (int qi = 0; qi < 4; qi++) {
            int gq = tok_q0 + q0 + qi;
#pragma unroll
            for (int ji = 0; ji < 4; ji++) {
                int gj = tok_k0 + j0 + ji;
                float v = s[qi][ji] * 0.125f + (1.0f - msk[j0 + ji]) * -1e9f;
                s[qi][ji] = (gj <= gq) ? v : -1e30f;
            }
        }
#pragma unroll
        for (int qi = 0; qi < 4; qi++) {
            float mt = fmaxf(fmaxf(s[qi][0], s[qi][1]), fmaxf(s[qi][2], s[qi][3]));
#pragma unroll
            for (int o = 1; o < 16; o <<= 1)
                mt = fmaxf(mt, __shfl_xor_sync(0xffffffffu, mt, o, 16));
            float Mn = fmaxf(M[qi], mt);
            float sc = expf(M[qi] - Mn);
            float ps = 0.f;
#pragma unroll
            for (int ji = 0; ji < 4; ji++) {
                float pv = expf(s[qi][ji] - Mn);
                s[qi][ji] = pv;
                ps += pv;
            }
            L[qi] = L[qi] * sc + ps;
#pragma unroll
            for (int di = 0; di < 4; di++) O[qi][di] *= sc;
            M[qi] = Mn;
        }
#pragma unroll
        for (int qi = 0; qi < 4; qi++)
#pragma unroll
            for (int ji = 0; ji < 4; ji++)
                Pt[(j0 + ji) * 64 + q0 + qi] = s[qi][ji];
        __syncthreads();

        int d0 = lg * 4;
        for (int j = 0; j < 64; j++) {
            const float4 pv = *(const float4*)(Pt + j * 64 + q0);
            const float4 vv = *(const float4*)(Vs + j * 64 + d0);
            float pa[4] = {pv.x, pv.y, pv.z, pv.w};
            float va[4] = {vv.x, vv.y, vv.z, vv.w};
#pragma unroll
            for (int qi = 0; qi < 4; qi++)
#pragma unroll
                for (int di = 0; di < 4; di++)
                    O[qi][di] = fmaf(pa[qi], va[di], O[qi][di]);
        }
    }

#pragma unroll
    for (int qi = 0; qi < 4; qi++) {
        float l = L[qi];
#pragma unroll
        for (int o = 1; o < 16; o <<= 1)
            l += __shfl_xor_sync(0xffffffffu, l, o, 16);
        float inv = 1.0f / l;
        int col = h * HD + lg * 4;
        unsigned short* base = outaug + (size_t)(b * SS + tok_q0 + q0 + qi) * 3 * HH + col;
        ushort4 hv, lv;
        unsigned short hu, lu;
        split_bf16(O[qi][0] * inv, hu, lu); hv.x = hu; lv.x = lu;
        split_bf16(O[qi][1] * inv, hu, lu); hv.y = hu; lv.y = lu;
        split_bf16(O[qi][2] * inv, hu, lu); hv.z = hu; lv.z = lu;
        split_bf16(O[qi][3] * inv, hu, lu); hv.w = hu; lv.w = lu;
        *(ushort4*)(base) = hv;
        *(ushort4*)(base + HH) = lv;
        *(ushort4*)(base + 2 * HH) = hv;
    }
}

// ---------------- add + layernorm (writes h fp32 + narrow aug) -------------------
__global__ void add_ln_kernel(float* __restrict__ h, const float* __restrict__ a,
                              const float* __restrict__ g, const float* __restrict__ bt,
                              unsigned short* __restrict__ aug)
{
    int row = blockIdx.x;
    int tid = threadIdx.x;
    __shared__ float buf[HH];
    __shared__ float red[256];

    float* hrow = h + (size_t)row * HH;
    const float* arow = a + (size_t)row * HH;
    unsigned short* grow = aug + (size_t)row * 3 * HH;

    float lsum = 0.f;
#pragma unroll
    for (int i = 0; i < 3; i++) {
        int idx = tid + i * 256;
        float v = hrow[idx] + arow[idx];
        buf[idx] = v;
        lsum += v;
    }
    red[tid] = lsum;
    __syncthreads();
    for (int off = 128; off > 0; off >>= 1) {
        if (tid < off) red[tid] += red[tid + off];
        __syncthreads();
    }
    float mean = red[0] * (1.0f / HH);
    __syncthreads();

    float lvar = 0.f;
#pragma unroll
    for (int i = 0; i < 3; i++) {
        int idx = tid + i * 256;
        float d = buf[idx] - mean;
        lvar += d * d;
    }
    red[tid] = lvar;
    __syncthreads();
    for (int off = 128; off > 0; off >>= 1) {
        if (tid < off) red[tid] += red[tid + off];
        __syncthreads();
    }
    float rstd = rsqrtf(red[0] * (1.0f / HH) + 1e-5f);

#pragma unroll
    for (int i = 0; i < 3; i++) {
        int idx = tid + i * 256;
        float y = g[idx] * ((buf[idx] - mean) * rstd) + bt[idx];
        hrow[idx] = y;
        unsigned short hu, lu;
        split_bf16(y, hu, lu);
        grow[idx] = hu;
        grow[HH + idx] = lu;
        grow[2 * HH + idx] = hu;
    }
}

// ---------------- vocab softmax (online) -----------------------------------------
__global__ void softmax_kernel(const float* __restrict__ x, float* __restrict__ p)
{
    int row = blockIdx.x;
    int tid = threadIdx.x;
    __shared__ float rm[256], rl[256];
    const float* xr = x + (size_t)row * VV;
    float* pr = p + (size_t)row * VV;

    float m = -3.0e38f, l = 0.f;
    for (int i = tid; i < VV; i += 256) {
        float v = xr[i];
        if (v > m) { l = l * expf(m - v) + 1.0f; m = v; }
        else l += expf(v - m);
    }
    rm[tid] = m; rl[tid] = l;
    __syncthreads();
    for (int off = 128; off > 0; off >>= 1) {
        if (tid < off) {
            float m2 = rm[tid + off], l2 = rl[tid + off];
            float Mx = fmaxf(rm[tid], m2);
            rl[tid] = rl[tid] * expf(rm[tid] - Mx) + l2 * expf(m2 - Mx);
            rm[tid] = Mx;
        }
        __syncthreads();
    }
    float Mx = rm[0];
    float inv = 1.0f / rl[0];

    for (int i = tid; i < VV; i += 256) pr[i] = expf(xr[i] - Mx) * inv;
}

// ---------------- launch --------------------------------------------------------
extern "C" void kernel_launch(void* const* d_in, const int* in_sizes, int n_in,
                              void* d_out, int out_size)
{
    const int*   ids      = (const int*)d_in[0];
    const float* seq_mask = (const float*)d_in[1];
    const float* bpe      = (const float*)d_in[2];
    const float* pos      = (const float*)d_in[3];
    const float* qkv_w    = (const float*)d_in[4];
    const float* qkv_b    = (const float*)d_in[5];
    const float* res_w    = (const float*)d_in[6];
    const float* res_b    = (const float*)d_in[7];
    const float* ln1_g    = (const float*)d_in[8];
    const float* ln1_b    = (const float*)d_in[9];
    const float* ff1_w    = (const float*)d_in[10];
    const float* ff1_b    = (const float*)d_in[11];
    const float* ff2_w    = (const float*)d_in[12];
    const float* ff2_b    = (const float*)d_in[13];
    const float* ln2_g    = (const float*)d_in[14];
    const float* ln2_b    = (const float*)d_in[15];
    const float* pred_w   = (const float*)d_in[16];
    float* out = (float*)d_out;

    float *hP, *qkvP, *aP, *bP;
    unsigned short *waug, *augN, *augW;
    cudaGetSymbolAddress((void**)&hP, g_h);
    cudaGetSymbolAddress((void**)&qkvP, g_qkv);
    cudaGetSymbolAddress((void**)&aP, g_a);
    cudaGetSymbolAddress((void**)&bP, g_b);
    cudaGetSymbolAddress((void**)&waug, g_waug);
    cudaGetSymbolAddress((void**)&augN, g_augN);
    cudaGetSymbolAddress((void**)&augW, g_augW);

    cudaFuncSetAttribute(gemm_mma_kernel, cudaFuncAttributeMaxDynamicSharedMemorySize,
                         GEMM_SMEM);
    cudaFuncSetAttribute(attn_tile_kernel, cudaFuncAttributeMaxDynamicSharedMemorySize,
                         ATTN_SMEM);

    embed_kernel<<<MM, 256>>>(ids, bpe, pos, hP, augN);

    for (int l = 0; l < LL; l++) {
        wt_conv_kernel<<<dim3(TH / 32, HH / 32), dim3(32, 8)>>>(
            qkv_w + (size_t)l * QKV_SZ, waug + (size_t)3 * (OFF_QKV + (size_t)l * QKV_SZ), HH, TH);
        wt_conv_kernel<<<dim3(HH / 32, HH / 32), dim3(32, 8)>>>(
            res_w + (size_t)l * RES_SZ, waug + (size_t)3 * (OFF_RES + (size_t)l * RES_SZ), HH, HH);
        wt_conv_kernel<<<dim3(4 * HH / 32, HH / 32), dim3(32, 8)>>>(
            ff1_w + (size_t)l * FF1_SZ, waug + (size_t)3 * (OFF_FF1 + (size_t)l * FF1_SZ), HH, 4 * HH);
        wt_conv_kernel<<<dim3(HH / 32, 4 * HH / 32), dim3(32, 8)>>>(
            ff2_w + (size_t)l * FF2_SZ, waug + (size_t)3 * (OFF_FF2 + (size_t)l * FF2_SZ), 4 * HH, HH);

        gemm_mma_kernel<<<dim3(TH / 128, MM / 128), 256, GEMM_SMEM>>>(
            augN, waug + (size_t)3 * (OFF_QKV + (size_t)l * QKV_SZ),
            qkv_b + (size_t)l * TH, qkvP, nullptr, nullptr, MM, TH, 3 * HH, 0, 1);

        attn_tile_kernel<<<dim3(SS / 64, NHD, BB), 256, ATTN_SMEM>>>(qkvP, seq_mask, augN);

        gemm_mma_kernel<<<dim3(HH / 128, MM / 128, 3), 256, GEMM_SMEM>>>(
            augN, waug + (size_t)3 * (OFF_RES + (size_t)l * RES_SZ),
            nullptr, nullptr, nullptr, qkvP, MM, HH, 3 * HH, 0, 3);
        reduce3_bias_kernel<<<MM, 256>>>(qkvP, res_b + (size_t)l * HH, bP, HH);

        add_ln_kernel<<<MM, 256>>>(hP, bP, ln1_g + (size_t)l * HH, ln1_b + (size_t)l * HH, augN);

        gemm_mma_kernel<<<dim3(4 * HH / 128, MM / 128), 256, GEMM_SMEM>>>(
            augN, waug + (size_t)3 * (OFF_FF1 + (size_t)l * FF1_SZ),
            ff1_b + (size_t)l * 4 * HH, nullptr, augW, nullptr, MM, 4 * HH, 3 * HH, 1, 1);

        gemm_mma_kernel<<<dim3(HH / 128, MM / 128, 3), 256, GEMM_SMEM>>>(
            augW, waug + (size_t)3 * (OFF_FF2 + (size_t)l * FF2_SZ),
            nullptr, nullptr, nullptr, qkvP, MM, HH, 3 * 4 * HH, 0, 3);
        reduce3_bias_kernel<<<MM, 256>>>(qkvP, ff2_b + (size_t)l * HH, aP, HH);

        add_ln_kernel<<<MM, 256>>>(hP, aP, ln2_g + (size_t)l * HH, ln2_b + (size_t)l * HH, augN);
    }

    wt_conv_kernel<<<dim3(VV / 32, HH / 32), dim3(32, 8)>>>(
        pred_w, waug + (size_t)3 * OFF_PRED, HH, VV);
    gemm_mma_kernel<<<dim3(VV / 128, MM / 128), 256, GEMM_SMEM>>>(
        augN, waug + (size_t)3 * OFF_PRED, nullptr, out, nullptr, nullptr, MM, VV, 3 * HH, 0, 1);

    softmax_kernel<<<MM, 256>>>(out, out + (size_t)MM * VV);
}